// round 12
// baseline (speedup 1.0000x reference)
#include <cuda_runtime.h>
#include <cuda_fp16.h>
#include <cstdint>

#define ROWS 16384      // B*S
#define CH   4096
#define NHD  8
#define IGD  128
#define TGD  384
#define FGD  512
#define ISZ  1024
#define NSEG 8
#define SEGL 512        // 4096 / NSEG

// ---------------- scratch ----------------
__device__ float g_csum[(size_t)ROWS * CH];        // GEMM out (fp32), scan source
__device__ float g_part[(size_t)4 * NSEG * CH];    // segment sums

__device__ __align__(16) uint16_t scan16[(size_t)ROWS * CH];        // scan result (fp16, LN input)
__device__ __align__(16) uint16_t gate16[(size_t)ROWS * NHD * TGD]; // gates fp16
__device__ __align__(16) uint16_t lci16 [(size_t)ROWS * ISZ];
__device__ __align__(16) uint16_t rci16 [(size_t)ROWS * ISZ];

// ---------------- activation planes: single fp16 ----------------
__device__ __align__(16) uint16_t is_p  [(size_t)ROWS * ISZ];
__device__ __align__(16) uint16_t cell_p[(size_t)ROWS * NHD * TGD];
__device__ __align__(16) uint16_t hpre_p[(size_t)ROWS * NHD * FGD];
__device__ __align__(16) uint16_t hp_p  [(size_t)ROWS * NHD * FGD];
__device__ __align__(16) uint16_t pre_p [(size_t)ROWS * ISZ];
// ---------------- weight planes: single fp16, transposed [N][K] ----------------
__device__ __align__(16) uint16_t wcs_p[(size_t)CH * ISZ];
__device__ __align__(16) uint16_t wx_p [(size_t)ISZ * ISZ];
__device__ __align__(16) uint16_t wg_p [(size_t)NHD * TGD * TGD];
__device__ __align__(16) uint16_t wf1_p[(size_t)NHD * FGD * TGD];
__device__ __align__(16) uint16_t wf2_p[(size_t)NHD * IGD * FGD];
__device__ __align__(16) uint16_t wo_p [(size_t)ISZ * ISZ];

// ---------------- helpers ----------------
__device__ __forceinline__ uint32_t smem_u32(const void* p) {
    uint32_t a;
    asm("{ .reg .u64 t; cvta.to.shared.u64 t, %1; cvt.u32.u64 %0, t; }" : "=r"(a) : "l"(p));
    return a;
}
#define CP16(dst, src) asm volatile("cp.async.cg.shared.global [%0], [%1], 16;" :: "r"(dst), "l"(src))
#define CP_COMMIT()    asm volatile("cp.async.commit_group;" ::: "memory")

__device__ __forceinline__ void ldm4(uint32_t& r0, uint32_t& r1, uint32_t& r2, uint32_t& r3, uint32_t a) {
    asm volatile("ldmatrix.sync.aligned.m8n8.x4.shared.b16 {%0,%1,%2,%3}, [%4];"
                 : "=r"(r0), "=r"(r1), "=r"(r2), "=r"(r3) : "r"(a));
}
__device__ __forceinline__ void mma16816(float* d, const uint32_t* a, const uint32_t* b) {
    asm volatile("mma.sync.aligned.m16n8k16.row.col.f32.f16.f16.f32 "
                 "{%0,%1,%2,%3},{%4,%5,%6,%7},{%8,%9},{%0,%1,%2,%3};"
                 : "+f"(d[0]), "+f"(d[1]), "+f"(d[2]), "+f"(d[3])
                 : "r"(a[0]), "r"(a[1]), "r"(a[2]), "r"(a[3]), "r"(b[0]), "r"(b[1]));
}
__device__ __forceinline__ uint32_t pack2h(float x, float y) {
    __half2 v = __floats2half2_rn(x, y);
    return *(uint32_t*)&v;
}
__device__ __forceinline__ uint2 pack4h(float4 v) {
    uint2 r;
    r.x = pack2h(v.x, v.y);
    r.y = pack2h(v.z, v.w);
    return r;
}
__device__ __forceinline__ float2 unp2(uint32_t u) { return __half22float2(*(__half2*)&u); }

// ---------------- fp16 tensor-core GEMM, double-buffered ----------------
// FLAGS: 1 mask, 2 residual(fp32 out), 4 fp16-out remap (out_x), 8 fused-combine (ffn2), 16 fp16-out plain
#define P_A  0
#define P_B  8192
#define STG  16384
#define SMT  32768

template <int FLAGS>
__global__ void __launch_bounds__(256, 2) hgemm_k(
    const uint16_t* __restrict__ Ap, int lda, int aoff,
    const uint16_t* __restrict__ Bp, long boff,
    const float* __restrict__ bias, int biasoff,
    float* __restrict__ C, int ldc, int coff,
    uint16_t* __restrict__ Cp,
    int N, int K,
    const unsigned char* __restrict__ mask,
    const float* __restrict__ resid,
    const uint16_t* __restrict__ g16,   // gates (FLAG8)
    const uint16_t* __restrict__ l16, const uint16_t* __restrict__ r16)
{
    extern __shared__ char smem[];
    const uint32_t sb = smem_u32(smem);
    const int tid = threadIdx.x, wid = tid >> 5, lane = tid & 31;

    Ap += (long)blockIdx.z * aoff;
    Bp += (long)blockIdx.z * boff;
    bias += (long)blockIdx.z * biasoff;
    C  += (long)blockIdx.z * coff;
    Cp += (FLAGS & 16) ? (long)blockIdx.z * coff : 0;

    const int m0 = blockIdx.y * 128;
    const int n0 = blockIdx.x * 128;
    const int warpM = (wid & 1) * 64;
    const int warpN = (wid >> 1) * 32;

    const int rowA = warpM + (lane & 15);
    const int hiA  = (lane >> 4) & 1;
    const int swA  = (rowA >> 1) & 3;
    const uint32_t aRow = sb + P_A + (uint32_t)rowA * 64;

    const int rowB = warpN + (lane & 7) + ((lane & 16) >> 1);
    const int hiB  = (lane >> 3) & 1;
    const int swB  = (rowB >> 1) & 3;
    const uint32_t bRow = sb + P_B + (uint32_t)rowB * 64;

    const int su0 = tid, su1 = tid + 256;
    const int sr0 = su0 >> 2, sc0 = su0 & 3;
    const int sr1 = su1 >> 2, sc1 = su1 & 3;
    const uint32_t sd0 = (uint32_t)sr0 * 64 + ((uint32_t)(sc0 ^ ((sr0 >> 1) & 3)) << 4);
    const uint32_t sd1 = (uint32_t)sr1 * 64 + ((uint32_t)(sc1 ^ ((sr1 >> 1) & 3)) << 4);

    float acc[4][4][4];
#pragma unroll
    for (int i = 0; i < 4; i++)
#pragma unroll
        for (int j = 0; j < 4; j++)
#pragma unroll
            for (int q = 0; q < 4; q++) acc[i][j][q] = 0.f;

    const int nch = K >> 5;

#define STAGE(c, bs) do { \
        const int _k0 = (c) << 5; \
        const uint32_t _b = sb + (bs) * STG; \
        size_t _sa = (size_t)(m0 + sr0) * lda + _k0 + sc0 * 8; \
        CP16(_b + P_A + sd0, Ap + _sa); \
        size_t _sb2 = (size_t)(n0 + sr0) * K + _k0 + sc0 * 8; \
        CP16(_b + P_B + sd0, Bp + _sb2); \
        _sa = (size_t)(m0 + sr1) * lda + _k0 + sc1 * 8; \
        CP16(_b + P_A + sd1, Ap + _sa); \
        _sb2 = (size_t)(n0 + sr1) * K + _k0 + sc1 * 8; \
        CP16(_b + P_B + sd1, Bp + _sb2); \
        CP_COMMIT(); \
    } while (0)

    STAGE(0, 0);
    for (int c = 0; c < nch; c++) {
        const int bs = c & 1;
        if (c + 1 < nch) {
            STAGE(c + 1, bs ^ 1);
            asm volatile("cp.async.wait_group 1;" ::: "memory");
        } else {
            asm volatile("cp.async.wait_group 0;" ::: "memory");
        }
        __syncthreads();

        const uint32_t bb = (uint32_t)bs * STG;
#pragma unroll
        for (int ks = 0; ks < 2; ks++) {
            const uint32_t ca = ((uint32_t)((2 * ks + hiA) ^ swA)) << 4;
            const uint32_t cb = ((uint32_t)((2 * ks + hiB) ^ swB)) << 4;
            uint32_t bf[4][2];
            ldm4(bf[0][0], bf[0][1], bf[1][0], bf[1][1], bRow + bb + cb);
            ldm4(bf[2][0], bf[2][1], bf[3][0], bf[3][1], bRow + bb + 1024 + cb);
#pragma unroll
            for (int mf = 0; mf < 4; mf++) {
                uint32_t af[4];
                ldm4(af[0], af[1], af[2], af[3], aRow + bb + mf * 1024 + ca);
#pragma unroll
                for (int nf = 0; nf < 4; nf++)
                    mma16816(acc[mf][nf], af, bf[nf]);
            }
        }
        __syncthreads();
    }
#undef STAGE

    // ---------------- epilogue ----------------
#pragma unroll
    for (int mf = 0; mf < 4; mf++) {
        long rA = m0 + warpM + mf * 16 + (lane >> 2);
        long rB = rA + 8;
        float zfA = 1.f, zfB = 1.f;
        if (FLAGS & 1) { zfA = mask[rA] ? 0.f : 1.f; zfB = mask[rB] ? 0.f : 1.f; }
#pragma unroll
        for (int nf = 0; nf < 4; nf++) {
            int gn = n0 + warpN + nf * 8 + (lane & 3) * 2;
            float b0 = bias[gn], b1 = bias[gn + 1];
            float x0 = acc[mf][nf][0] + b0, x1 = acc[mf][nf][1] + b1;
            float y0 = acc[mf][nf][2] + b0, y1 = acc[mf][nf][3] + b1;
            if (FLAGS & 1) { x0 *= zfA; x1 *= zfA; y0 *= zfB; y1 *= zfB; }
            if (FLAGS & 2) {
                x0 += resid[rA * N + gn]; x1 += resid[rA * N + gn + 1];
                y0 += resid[rB * N + gn]; y1 += resid[rB * N + gn + 1];
            }
            if (FLAGS & 4) {
                int cn = (gn >> 7) * TGD + IGD + (gn & 127);
                *(uint32_t*)&Cp[rA * ldc + cn] = pack2h(x0, x1);
                *(uint32_t*)&Cp[rB * ldc + cn] = pack2h(y0, y1);
            } else if (FLAGS & 8) {
                int gc = blockIdx.z * IGD + gn;
                const uint16_t* gbA = g16 + rA * (NHD * TGD) + blockIdx.z * TGD;
                const uint16_t* gbB = g16 + rB * (NHD * TGD) + blockIdx.z * TGD;
                float2 lgA = unp2(*(const uint32_t*)&gbA[gn]);
                float2 igA = unp2(*(const uint32_t*)&gbA[IGD + gn]);
                float2 rgA = unp2(*(const uint32_t*)&gbA[2 * IGD + gn]);
                float2 lgB = unp2(*(const uint32_t*)&gbB[gn]);
                float2 igB = unp2(*(const uint32_t*)&gbB[IGD + gn]);
                float2 rgB = unp2(*(const uint32_t*)&gbB[2 * IGD + gn]);
                float2 liA = unp2(*(const uint32_t*)&l16[rA * ISZ + gc]);
                float2 riA = unp2(*(const uint32_t*)&r16[rA * ISZ + gc]);
                float2 liB = unp2(*(const uint32_t*)&l16[rB * ISZ + gc]);
                float2 riB = unp2(*(const uint32_t*)&r16[rB * ISZ + gc]);
                float o0 = liA.x * lgA.x + igA.x * x0 + riA.x * rgA.x;
                float o1 = liA.y * lgA.y + igA.y * x1 + riA.y * rgA.y;
                float o2 = liB.x * lgB.x + igB.x * y0 + riB.x * rgB.x;
                float o3 = liB.y * lgB.y + igB.y * y1 + riB.y * rgB.y;
                *(uint32_t*)&Cp[rA * ISZ + gc] = pack2h(o0, o1);
                *(uint32_t*)&Cp[rB * ISZ + gc] = pack2h(o2, o3);
            } else if (FLAGS & 16) {
                *(uint32_t*)&Cp[rA * ldc + gn] = pack2h(x0, x1);
                *(uint32_t*)&Cp[rB * ldc + gn] = pack2h(y0, y1);
            } else {
                *(float2*)(C + rA * ldc + gn) = make_float2(x0, x1);
                *(float2*)(C + rB * ldc + gn) = make_float2(y0, y1);
            }
        }
    }
}

// ---------------- conversion kernels ----------------
__global__ void __launch_bounds__(256) icvt_k(const float* __restrict__ src,
                                              uint16_t* __restrict__ p) {
    size_t i = (size_t)blockIdx.x * 256 + threadIdx.x;
    float4 v = ((const float4*)src)[i];
    ((uint2*)p)[i] = pack4h(v);
}

// W [K][N] fp32 -> single fp16 plane [N][K]
__global__ void __launch_bounds__(256) wsplit_k(const float* __restrict__ W,
                                                uint16_t* __restrict__ Tp,
                                                int K, int N) {
    __shared__ float tile[32][33];
    const int n0 = blockIdx.x * 32, k0 = blockIdx.y * 32;
    const float* Wp = W + (size_t)blockIdx.z * K * N;
    uint16_t* Hp = Tp + (size_t)blockIdx.z * K * N;
    int tx = threadIdx.x & 31, ty = threadIdx.x >> 5;
#pragma unroll
    for (int i = 0; i < 4; i++)
        tile[ty + 8 * i][tx] = Wp[(size_t)(k0 + ty + 8 * i) * N + n0 + tx];
    __syncthreads();
#pragma unroll
    for (int i = 0; i < 4; i++) {
        __half h = __float2half_rn(tile[tx][ty + 8 * i]);
        Hp[(size_t)(n0 + ty + 8 * i) * K + k0 + tx] = *(uint16_t*)&h;
    }
}

// ---------------- block reduce ----------------
__device__ __forceinline__ void block_reduce2(float& a, float& b) {
    __shared__ float sh[64];
    int lane = threadIdx.x & 31, wid = threadIdx.x >> 5;
#pragma unroll
    for (int o = 16; o > 0; o >>= 1) {
        a += __shfl_xor_sync(0xffffffffu, a, o);
        b += __shfl_xor_sync(0xffffffffu, b, o);
    }
    if (lane == 0) { sh[wid] = a; sh[32 + wid] = b; }
    __syncthreads();
    if (threadIdx.x < 32) {
        a = (lane < 8) ? sh[lane] : 0.f;
        b = (lane < 8) ? sh[32 + lane] : 0.f;
#pragma unroll
        for (int o = 4; o > 0; o >>= 1) {
            a += __shfl_xor_sync(0xffffffffu, a, o);
            b += __shfl_xor_sync(0xffffffffu, b, o);
        }
        if (lane == 0) { sh[0] = a; sh[32] = b; }
    }
    __syncthreads();
    a = sh[0]; b = sh[32];
}

// ---------------- segmented cumsum (fp32 source; fp16 scan output) ----------------
__global__ void __launch_bounds__(256) cumsumA_k() {
    int idx = blockIdx.x * 256 + threadIdx.x;     // (b*NSEG+seg)*4096 + c
    int c = idx & 4095;
    int t = idx >> 12;
    int b = t >> 3, seg = t & 7;
    const float* p = g_csum + ((size_t)b << 24) + (size_t)(seg * SEGL) * CH + c;
    float s = 0.f;
#pragma unroll 8
    for (int i = 0; i < SEGL; i++) s += p[(size_t)i * CH];
    g_part[idx] = s;
}

__global__ void __launch_bounds__(256) cumsumC_k() {
    int idx = blockIdx.x * 256 + threadIdx.x;
    int c = idx & 4095;
    int t = idx >> 12;
    int b = t >> 3, seg = t & 7;
    const float* p = g_csum + ((size_t)b << 24) + (size_t)(seg * SEGL) * CH + c;
    uint16_t* q = scan16 + ((size_t)b << 24) + (size_t)(seg * SEGL) * CH + c;
    float acc = 0.f;
    if (c < 2048) {
#pragma unroll
        for (int s2 = 0; s2 < NSEG; s2++)
            if (s2 < seg) acc += g_part[((b * NSEG + s2) << 12) + c];
#pragma unroll 8
        for (int i = 0; i < SEGL; i++) {
            acc += p[(size_t)i * CH];
            __half h = __float2half_rn(acc);
            q[(size_t)i * CH] = *(uint16_t*)&h;
        }
    } else {
#pragma unroll
        for (int s2 = 0; s2 < NSEG; s2++)
            if (s2 > seg) acc += g_part[((b * NSEG + s2) << 12) + c];
#pragma unroll 8
        for (int i = SEGL - 1; i >= 0; i--) {
            acc += p[(size_t)i * CH];
            __half h = __float2half_rn(acc);
            q[(size_t)i * CH] = *(uint16_t*)&h;
        }
    }
}

// ---------------- LN lc/rc (fp16 in) -> cell plane + relu'd lci/rci (fp16) ----------------
__global__ void __launch_bounds__(256) ln_lcrc_k(
    const float* __restrict__ gl, const float* __restrict__ bl,
    const float* __restrict__ gr, const float* __restrict__ br_)
{
    const int row = blockIdx.x, side = blockIdx.y;
    const uint4* x4 = (const uint4*)(scan16 + (size_t)row * CH + side * 2048);
    uint4 u = x4[threadIdx.x];                  // 8 halves
    float2 p0 = unp2(u.x), p1 = unp2(u.y), p2 = unp2(u.z), p3 = unp2(u.w);
    float s  = p0.x + p0.y + p1.x + p1.y + p2.x + p2.y + p3.x + p3.y;
    float ss = p0.x * p0.x + p0.y * p0.y + p1.x * p1.x + p1.y * p1.y
             + p2.x * p2.x + p2.y * p2.y + p3.x * p3.x + p3.y * p3.y;
    block_reduce2(s, ss);
    float m  = s * (1.f / 2048.f);
    float rs = rsqrtf(ss * (1.f / 2048.f) - m * m + 1e-6f);

    const float* gg = side ? gr  : gl;
    const float* bb = side ? br_ : bl;
    const int c = threadIdx.x * 8;
    float4 g0 = *(const float4*)(gg + c), g1 = *(const float4*)(gg + c + 4);
    float4 b0 = *(const float4*)(bb + c), b1 = *(const float4*)(bb + c + 4);
    float4 o0, o1;
    o0.x = (p0.x - m) * rs * g0.x + b0.x;
    o0.y = (p0.y - m) * rs * g0.y + b0.y;
    o0.z = (p1.x - m) * rs * g0.z + b0.z;
    o0.w = (p1.y - m) * rs * g0.w + b0.w;
    o1.x = (p2.x - m) * rs * g1.x + b1.x;
    o1.y = (p2.y - m) * rs * g1.y + b1.y;
    o1.z = (p3.x - m) * rs * g1.z + b1.z;
    o1.w = (p3.y - m) * rs * g1.w + b1.w;

    if (c < 1024) {   // gate part -> cell
        int h = c >> 7, ig = c & 127;
        size_t o16 = (size_t)row * (NHD * TGD) + h * TGD + side * 256 + ig;
        uint4 w;
        uint2 a = pack4h(o0), b2 = pack4h(o1);
        w.x = a.x; w.y = a.y; w.z = b2.x; w.w = b2.y;
        *(uint4*)&cell_p[o16] = w;
    } else {          // input part -> relu -> lci/rci
        o0.x = fmaxf(o0.x, 0.f); o0.y = fmaxf(o0.y, 0.f);
        o0.z = fmaxf(o0.z, 0.f); o0.w = fmaxf(o0.w, 0.f);
        o1.x = fmaxf(o1.x, 0.f); o1.y = fmaxf(o1.y, 0.f);
        o1.z = fmaxf(o1.z, 0.f); o1.w = fmaxf(o1.w, 0.f);
        uint16_t* ibuf = side ? rci16 : lci16;
        uint4 w;
        uint2 a = pack4h(o0), b2 = pack4h(o1);
        w.x = a.x; w.y = a.y; w.z = b2.x; w.w = b2.y;
        *(uint4*)&ibuf[(size_t)row * ISZ + (c - 1024)] = w;
    }
}

// ---------------- LN gates + sigmoid (fp16 in place) ----------------
__global__ void __launch_bounds__(256) ln_g_k(const float* __restrict__ gg,
                                              const float* __restrict__ bg) {
    const int row = blockIdx.x;
    uint2* x2 = (uint2*)(gate16 + (size_t)row * (NHD * TGD));
    float4 v[3];
    float s = 0.f, ss = 0.f;
#pragma unroll
    for (int k = 0; k < 3; k++) {
        uint2 u = x2[threadIdx.x + k * 256];
        float2 a = unp2(u.x), b = unp2(u.y);
        v[k] = make_float4(a.x, a.y, b.x, b.y);
        s  += v[k].x + v[k].y + v[k].z + v[k].w;
        ss += v[k].x * v[k].x + v[k].y * v[k].y + v[k].z * v[k].z + v[k].w * v[k].w;
    }
    block_reduce2(s, ss);
    float m  = s * (1.f / 3072.f);
    float rs = rsqrtf(ss * (1.f / 3072.f) - m * m + 1e-6f);
    const float4* g4 = (const float4*)gg;
    const float4* b4 = (const float4*)bg;
#pragma unroll
    for (int k = 0; k < 3; k++) {
        int c4 = threadIdx.x + k * 256;
        float4 gv = g4[c4], bv = b4[c4], xv = v[k];
        float4 o;
        o.x = 1.f / (1.f + __expf(-((xv.x - m) * rs * gv.x + bv.x)));
        o.y = 1.f / (1.f + __expf(-((xv.y - m) * rs * gv.y + bv.y)));
        o.z = 1.f / (1.f + __expf(-((xv.z - m) * rs * gv.z + bv.z)));
        o.w = 1.f / (1.f + __expf(-((xv.w - m) * rs * gv.w + bv.w)));
        uint2 w;
        w.x = pack2h(o.x, o.y);
        w.y = pack2h(o.z, o.w);
        x2[c4] = w;
    }
}

// ---------------- LN ffn hidden (fp16 in) + relu -> hp plane ----------------
__global__ void __launch_bounds__(256) ln_f_k(const float* __restrict__ gf,
                                              const float* __restrict__ bf) {
    const int row = blockIdx.x;
    const uint2* x2 = (const uint2*)(hpre_p + (size_t)row * (NHD * FGD));
    float4 v[4];
    float s = 0.f, ss = 0.f;
#pragma unroll
    for (int k = 0; k < 4; k++) {
        uint2 u = x2[threadIdx.x + k * 256];
        float2 a = unp2(u.x), b = unp2(u.y);
        v[k] = make_float4(a.x, a.y, b.x, b.y);
        s  += v[k].x + v[k].y + v[k].z + v[k].w;
        ss += v[k].x * v[k].x + v[k].y * v[k].y + v[k].z * v[k].z + v[k].w * v[k].w;
    }
    block_reduce2(s, ss);
    float m  = s * (1.f / 4096.f);
    float rs = rsqrtf(ss * (1.f / 4096.f) - m * m + 1e-6f);
    const float4* g4 = (const float4*)gf;
    const float4* b4 = (const float4*)bf;
#pragma unroll
    for (int k = 0; k < 4; k++) {
        int c4 = threadIdx.x + k * 256;
        float4 gv = g4[c4], bv = b4[c4], xv = v[k];
        float4 o;
        o.x = fmaxf((xv.x - m) * rs * gv.x + bv.x, 0.f);
        o.y = fmaxf((xv.y - m) * rs * gv.y + bv.y, 0.f);
        o.z = fmaxf((xv.z - m) * rs * gv.z + bv.z, 0.f);
        o.w = fmaxf((xv.w - m) * rs * gv.w + bv.w, 0.f);
        *(uint2*)&hp_p[(size_t)row * (NHD * FGD) + c4 * 4] = pack4h(o);
    }
}

// ---------------- host ----------------
extern "C" void kernel_launch(void* const* d_in, const int* in_sizes, int n_in,
                              void* d_out, int out_size) {
    const float* inputs = (const float*)d_in[0];
    const unsigned char* mask = (const unsigned char*)d_in[1];
    const float* W_csum = (const float*)d_in[2];
    const float* b_csum = (const float*)d_in[3];
    const float* W_x    = (const float*)d_in[4];
    const float* b_x    = (const float*)d_in[5];
    const float* gl     = (const float*)d_in[6];
    const float* bel    = (const float*)d_in[7];
    const float* gr     = (const float*)d_in[8];
    const float* ber    = (const float*)d_in[9];
    const float* ggain  = (const float*)d_in[10];
    const float* beg    = (const float*)d_in[11];
    const float* gf     = (const float*)d_in[12];
    const float* bef    = (const float*)d_in[13];
    const float* W_g    = (const float*)d_in[14];
    const float* b_g    = (const float*)d_in[15];
    const float* W_f1   = (const float*)d_in[16];
    const float* b_f1   = (const float*)d_in[17];
    const float* W_f2   = (const float*)d_in[18];
    const float* b_f2   = (const float*)d_in[19];
    const float* W_o    = (const float*)d_in[20];
    const float* b_o    = (const float*)d_in[21];
    float* out = (float*)d_out;

    float* p_csum;
    cudaGetSymbolAddress((void**)&p_csum, g_csum);
    uint16_t *pg16, *pl16, *pr16;
    cudaGetSymbolAddress((void**)&pg16,  gate16);
    cudaGetSymbolAddress((void**)&pl16,  lci16);
    cudaGetSymbolAddress((void**)&pr16,  rci16);
    uint16_t *pis, *pcell, *phpre, *php, *ppre;
    uint16_t *pwcs, *pwx, *pwg, *pwf1, *pwf2, *pwo;
    cudaGetSymbolAddress((void**)&pis,   is_p);
    cudaGetSymbolAddress((void**)&pcell, cell_p);
    cudaGetSymbolAddress((void**)&phpre, hpre_p);
    cudaGetSymbolAddress((void**)&php,   hp_p);
    cudaGetSymbolAddress((void**)&ppre,  pre_p);
    cudaGetSymbolAddress((void**)&pwcs, wcs_p);
    cudaGetSymbolAddress((void**)&pwx,  wx_p);
    cudaGetSymbolAddress((void**)&pwg,  wg_p);
    cudaGetSymbolAddress((void**)&pwf1, wf1_p);
    cudaGetSymbolAddress((void**)&pwf2, wf2_p);
    cudaGetSymbolAddress((void**)&pwo,  wo_p);

    cudaFuncSetAttribute(hgemm_k<1>,  cudaFuncAttributeMaxDynamicSharedMemorySize, SMT);
    cudaFuncSetAttribute(hgemm_k<2>,  cudaFuncAttributeMaxDynamicSharedMemorySize, SMT);
    cudaFuncSetAttribute(hgemm_k<4>,  cudaFuncAttributeMaxDynamicSharedMemorySize, SMT);
    cudaFuncSetAttribute(hgemm_k<8>,  cudaFuncAttributeMaxDynamicSharedMemorySize, SMT);
    cudaFuncSetAttribute(hgemm_k<16>, cudaFuncAttributeMaxDynamicSharedMemorySize, SMT);

    dim3 blk(256);

    // ---- conversions ----
    icvt_k<<<ROWS * ISZ / 1024, blk>>>(inputs, pis);
    wsplit_k<<<dim3(CH / 32, ISZ / 32, 1), blk>>>(W_csum, pwcs, ISZ, CH);
    wsplit_k<<<dim3(ISZ / 32, ISZ / 32, 1), blk>>>(W_x, pwx, ISZ, ISZ);
    wsplit_k<<<dim3(TGD / 32, TGD / 32, NHD), blk>>>(W_g, pwg, TGD, TGD);
    wsplit_k<<<dim3(FGD / 32, TGD / 32, NHD), blk>>>(W_f1, pwf1, TGD, FGD);
    wsplit_k<<<dim3(IGD / 32, FGD / 32, NHD), blk>>>(W_f2, pwf2, FGD, IGD);
    wsplit_k<<<dim3(ISZ / 32, ISZ / 32, 1), blk>>>(W_o, pwo, ISZ, ISZ);

    // 1) csum GEMM (masked, fp32 out)
    hgemm_k<1><<<dim3(CH / 128, ROWS / 128, 1), blk, SMT>>>(
        pis, ISZ, 0, pwcs, 0, b_csum, 0,
        p_csum, CH, 0, nullptr, CH, ISZ, mask, nullptr, nullptr, nullptr, nullptr);
    // 2) out_x GEMM -> cell plane (remap)
    hgemm_k<4><<<dim3(ISZ / 128, ROWS / 128, 1), blk, SMT>>>(
        pis, ISZ, 0, pwx, 0, b_x, 0,
        nullptr, NHD * TGD, 0, pcell, ISZ, ISZ, nullptr, nullptr, nullptr, nullptr, nullptr);
    // 3) segmented cumsum (fp32 src -> fp16 scan out)
    cumsumA_k<<<512, 256>>>();
    cumsumC_k<<<512, 256>>>();
    // 4) LN lc/rc (fp16 in) -> cell + fp16 lci/rci
    ln_lcrc_k<<<dim3(ROWS, 2), 256>>>(gl, bel, gr, ber);
    // 5) gates GEMM (fp16 out)
    hgemm_k<16><<<dim3(TGD / 128, ROWS / 128, NHD), blk, SMT>>>(
        pcell, NHD * TGD, TGD, pwg, (long)TGD * TGD, b_g, TGD,
        nullptr, NHD * TGD, TGD, pg16, TGD, TGD, nullptr, nullptr, nullptr, nullptr, nullptr);
    // 6) LN gates + sigmoid (fp16 in place)
    ln_g_k<<<ROWS, 256>>>(ggain, beg);
    // 7) ffn1 GEMM -> fp16 pre-LN hidden
    hgemm_k<16><<<dim3(FGD / 128, ROWS / 128, NHD), blk, SMT>>>(
        pcell, NHD * TGD, TGD, pwf1, (long)FGD * TGD, b_f1, FGD,
        nullptr, NHD * FGD, FGD, phpre, FGD, TGD, nullptr, nullptr, nullptr, nullptr, nullptr);
    // 8) LN ffn + relu -> hp plane
    ln_f_k<<<ROWS, 256>>>(gf, bef);
    // 9) ffn2 GEMM + fused combine -> pre plane
    hgemm_k<8><<<dim3(IGD / 128, ROWS / 128, NHD), blk, SMT>>>(
        php, NHD * FGD, FGD, pwf2, (long)IGD * FGD, b_f2, IGD,
        nullptr, ISZ, IGD, ppre, IGD, FGD, nullptr, nullptr, pg16, pl16, pr16);
    // 10) final GEMM + residual
    hgemm_k<2><<<dim3(ISZ / 128, ROWS / 128, 1), blk, SMT>>>(
        ppre, ISZ, 0, pwo, 0, b_o, 0,
        out, ISZ, 0, nullptr, ISZ, ISZ, nullptr, inputs, nullptr, nullptr, nullptr);
}

// round 14
// speedup vs baseline: 1.6628x; 1.6628x over previous
#include <cuda_runtime.h>
#include <cuda_fp16.h>
#include <cstdint>

#define ROWS 16384      // B*S
#define CH   4096
#define NHD  8
#define IGD  128
#define TGD  384
#define FGD  512
#define ISZ  1024
#define NSEG 8
#define SEGL 512        // 4096 / NSEG
#define NTILE (ROWS / 128)   // 128 row tiles

// ---------------- scratch ----------------
__device__ float g_csum[(size_t)ROWS * CH];        // GEMM out + in-place scan (fp32)
__device__ float g_part[(size_t)4 * NSEG * CH];    // per-(batch,segment,col) sums
__device__ float g_tpart[(size_t)NTILE * CH];      // per-(row-tile,col) sums

__device__ __align__(16) uint16_t gate16[(size_t)ROWS * NHD * TGD]; // gates fp16
__device__ __align__(16) uint16_t lci16 [(size_t)ROWS * ISZ];
__device__ __align__(16) uint16_t rci16 [(size_t)ROWS * ISZ];

// ---------------- activation planes: single fp16 ----------------
__device__ __align__(16) uint16_t is_p  [(size_t)ROWS * ISZ];
__device__ __align__(16) uint16_t cell_p[(size_t)ROWS * NHD * TGD];
__device__ __align__(16) uint16_t hpre_p[(size_t)ROWS * NHD * FGD];
__device__ __align__(16) uint16_t hp_p  [(size_t)ROWS * NHD * FGD];
__device__ __align__(16) uint16_t pre_p [(size_t)ROWS * ISZ];
// ---------------- weight planes: single fp16, transposed [N][K] ----------------
__device__ __align__(16) uint16_t wcs_p[(size_t)CH * ISZ];
__device__ __align__(16) uint16_t wx_p [(size_t)ISZ * ISZ];
__device__ __align__(16) uint16_t wg_p [(size_t)NHD * TGD * TGD];
__device__ __align__(16) uint16_t wf1_p[(size_t)NHD * FGD * TGD];
__device__ __align__(16) uint16_t wf2_p[(size_t)NHD * IGD * FGD];
__device__ __align__(16) uint16_t wo_p [(size_t)ISZ * ISZ];

// ---------------- helpers ----------------
__device__ __forceinline__ uint32_t smem_u32(const void* p) {
    uint32_t a;
    asm("{ .reg .u64 t; cvta.to.shared.u64 t, %1; cvt.u32.u64 %0, t; }" : "=r"(a) : "l"(p));
    return a;
}
#define CP16(dst, src) asm volatile("cp.async.cg.shared.global [%0], [%1], 16;" :: "r"(dst), "l"(src))
#define CP_COMMIT()    asm volatile("cp.async.commit_group;" ::: "memory")

__device__ __forceinline__ void ldm4(uint32_t& r0, uint32_t& r1, uint32_t& r2, uint32_t& r3, uint32_t a) {
    asm volatile("ldmatrix.sync.aligned.m8n8.x4.shared.b16 {%0,%1,%2,%3}, [%4];"
                 : "=r"(r0), "=r"(r1), "=r"(r2), "=r"(r3) : "r"(a));
}
__device__ __forceinline__ void mma16816(float* d, const uint32_t* a, const uint32_t* b) {
    asm volatile("mma.sync.aligned.m16n8k16.row.col.f32.f16.f16.f32 "
                 "{%0,%1,%2,%3},{%4,%5,%6,%7},{%8,%9},{%0,%1,%2,%3};"
                 : "+f"(d[0]), "+f"(d[1]), "+f"(d[2]), "+f"(d[3])
                 : "r"(a[0]), "r"(a[1]), "r"(a[2]), "r"(a[3]), "r"(b[0]), "r"(b[1]));
}
__device__ __forceinline__ uint32_t pack2h(float x, float y) {
    __half2 v = __floats2half2_rn(x, y);
    return *(uint32_t*)&v;
}
__device__ __forceinline__ uint2 pack4h(float4 v) {
    uint2 r;
    r.x = pack2h(v.x, v.y);
    r.y = pack2h(v.z, v.w);
    return r;
}
__device__ __forceinline__ float2 unp2(uint32_t u) { return __half22float2(*(__half2*)&u); }

// ---------------- fp16 tensor-core GEMM, double-buffered ----------------
// FLAGS: 1 mask, 2 residual(fp32 out), 4 fp16-out remap (out_x), 8 fused-combine (ffn2),
//        16 fp16-out plain, 32 per-tile column sums -> g_tpart
#define P_A  0
#define P_B  8192
#define STG  16384
#define SMT  32768

template <int FLAGS>
__global__ void __launch_bounds__(256, 2) hgemm_k(
    const uint16_t* __restrict__ Ap, int lda, int aoff,
    const uint16_t* __restrict__ Bp, long boff,
    const float* __restrict__ bias, int biasoff,
    float* __restrict__ C, int ldc, int coff,
    uint16_t* __restrict__ Cp,
    int N, int K,
    const unsigned char* __restrict__ mask,
    const float* __restrict__ resid,
    const uint16_t* __restrict__ g16,   // gates (FLAG8)
    const uint16_t* __restrict__ l16, const uint16_t* __restrict__ r16)
{
    extern __shared__ char smem[];
    const uint32_t sb = smem_u32(smem);
    const int tid = threadIdx.x, wid = tid >> 5, lane = tid & 31;

    Ap += (long)blockIdx.z * aoff;
    Bp += (long)blockIdx.z * boff;
    bias += (long)blockIdx.z * biasoff;
    C  += (long)blockIdx.z * coff;
    Cp += (FLAGS & 16) ? (long)blockIdx.z * coff : 0;

    const int m0 = blockIdx.y * 128;
    const int n0 = blockIdx.x * 128;
    const int warpM = (wid & 1) * 64;
    const int warpN = (wid >> 1) * 32;

    const int rowA = warpM + (lane & 15);
    const int hiA  = (lane >> 4) & 1;
    const int swA  = (rowA >> 1) & 3;
    const uint32_t aRow = sb + P_A + (uint32_t)rowA * 64;

    const int rowB = warpN + (lane & 7) + ((lane & 16) >> 1);
    const int hiB  = (lane >> 3) & 1;
    const int swB  = (rowB >> 1) & 3;
    const uint32_t bRow = sb + P_B + (uint32_t)rowB * 64;

    const int su0 = tid, su1 = tid + 256;
    const int sr0 = su0 >> 2, sc0 = su0 & 3;
    const int sr1 = su1 >> 2, sc1 = su1 & 3;
    const uint32_t sd0 = (uint32_t)sr0 * 64 + ((uint32_t)(sc0 ^ ((sr0 >> 1) & 3)) << 4);
    const uint32_t sd1 = (uint32_t)sr1 * 64 + ((uint32_t)(sc1 ^ ((sr1 >> 1) & 3)) << 4);

    float acc[4][4][4];
#pragma unroll
    for (int i = 0; i < 4; i++)
#pragma unroll
        for (int j = 0; j < 4; j++)
#pragma unroll
            for (int q = 0; q < 4; q++) acc[i][j][q] = 0.f;

    const int nch = K >> 5;

#define STAGE(c, bs) do { \
        const int _k0 = (c) << 5; \
        const uint32_t _b = sb + (bs) * STG; \
        size_t _sa = (size_t)(m0 + sr0) * lda + _k0 + sc0 * 8; \
        CP16(_b + P_A + sd0, Ap + _sa); \
        size_t _sb2 = (size_t)(n0 + sr0) * K + _k0 + sc0 * 8; \
        CP16(_b + P_B + sd0, Bp + _sb2); \
        _sa = (size_t)(m0 + sr1) * lda + _k0 + sc1 * 8; \
        CP16(_b + P_A + sd1, Ap + _sa); \
        _sb2 = (size_t)(n0 + sr1) * K + _k0 + sc1 * 8; \
        CP16(_b + P_B + sd1, Bp + _sb2); \
        CP_COMMIT(); \
    } while (0)

    STAGE(0, 0);
    for (int c = 0; c < nch; c++) {
        const int bs = c & 1;
        if (c + 1 < nch) {
            STAGE(c + 1, bs ^ 1);
            asm volatile("cp.async.wait_group 1;" ::: "memory");
        } else {
            asm volatile("cp.async.wait_group 0;" ::: "memory");
        }
        __syncthreads();

        const uint32_t bb = (uint32_t)bs * STG;
#pragma unroll
        for (int ks = 0; ks < 2; ks++) {
            const uint32_t ca = ((uint32_t)((2 * ks + hiA) ^ swA)) << 4;
            const uint32_t cb = ((uint32_t)((2 * ks + hiB) ^ swB)) << 4;
            uint32_t bf[4][2];
            ldm4(bf[0][0], bf[0][1], bf[1][0], bf[1][1], bRow + bb + cb);
            ldm4(bf[2][0], bf[2][1], bf[3][0], bf[3][1], bRow + bb + 1024 + cb);
#pragma unroll
            for (int mf = 0; mf < 4; mf++) {
                uint32_t af[4];
                ldm4(af[0], af[1], af[2], af[3], aRow + bb + mf * 1024 + ca);
#pragma unroll
                for (int nf = 0; nf < 4; nf++)
                    mma16816(acc[mf][nf], af, bf[nf]);
            }
        }
        __syncthreads();
    }
#undef STAGE

    // ---------------- epilogue ----------------
    float colsum[8];
    if (FLAGS & 32) {
#pragma unroll
        for (int q = 0; q < 8; q++) colsum[q] = 0.f;
    }
#pragma unroll
    for (int mf = 0; mf < 4; mf++) {
        long rA = m0 + warpM + mf * 16 + (lane >> 2);
        long rB = rA + 8;
        float zfA = 1.f, zfB = 1.f;
        if (FLAGS & 1) { zfA = mask[rA] ? 0.f : 1.f; zfB = mask[rB] ? 0.f : 1.f; }
#pragma unroll
        for (int nf = 0; nf < 4; nf++) {
            int gn = n0 + warpN + nf * 8 + (lane & 3) * 2;
            float b0 = bias[gn], b1 = bias[gn + 1];
            float x0 = acc[mf][nf][0] + b0, x1 = acc[mf][nf][1] + b1;
            float y0 = acc[mf][nf][2] + b0, y1 = acc[mf][nf][3] + b1;
            if (FLAGS & 1) { x0 *= zfA; x1 *= zfA; y0 *= zfB; y1 *= zfB; }
            if (FLAGS & 32) {
                colsum[nf * 2]     += x0 + y0;
                colsum[nf * 2 + 1] += x1 + y1;
            }
            if (FLAGS & 2) {
                x0 += resid[rA * N + gn]; x1 += resid[rA * N + gn + 1];
                y0 += resid[rB * N + gn]; y1 += resid[rB * N + gn + 1];
            }
            if (FLAGS & 4) {
                int cn = (gn >> 7) * TGD + IGD + (gn & 127);
                *(uint32_t*)&Cp[rA * ldc + cn] = pack2h(x0, x1);
                *(uint32_t*)&Cp[rB * ldc + cn] = pack2h(y0, y1);
            } else if (FLAGS & 8) {
                int gc = blockIdx.z * IGD + gn;
                const uint16_t* gbA = g16 + rA * (NHD * TGD) + blockIdx.z * TGD;
                const uint16_t* gbB = g16 + rB * (NHD * TGD) + blockIdx.z * TGD;
                float2 lgA = unp2(*(const uint32_t*)&gbA[gn]);
                float2 igA = unp2(*(const uint32_t*)&gbA[IGD + gn]);
                float2 rgA = unp2(*(const uint32_t*)&gbA[2 * IGD + gn]);
                float2 lgB = unp2(*(const uint32_t*)&gbB[gn]);
                float2 igB = unp2(*(const uint32_t*)&gbB[IGD + gn]);
                float2 rgB = unp2(*(const uint32_t*)&gbB[2 * IGD + gn]);
                float2 liA = unp2(*(const uint32_t*)&l16[rA * ISZ + gc]);
                float2 riA = unp2(*(const uint32_t*)&r16[rA * ISZ + gc]);
                float2 liB = unp2(*(const uint32_t*)&l16[rB * ISZ + gc]);
                float2 riB = unp2(*(const uint32_t*)&r16[rB * ISZ + gc]);
                float o0 = liA.x * lgA.x + igA.x * x0 + riA.x * rgA.x;
                float o1 = liA.y * lgA.y + igA.y * x1 + riA.y * rgA.y;
                float o2 = liB.x * lgB.x + igB.x * y0 + riB.x * rgB.x;
                float o3 = liB.y * lgB.y + igB.y * y1 + riB.y * rgB.y;
                *(uint32_t*)&Cp[rA * ISZ + gc] = pack2h(o0, o1);
                *(uint32_t*)&Cp[rB * ISZ + gc] = pack2h(o2, o3);
            } else if (FLAGS & 16) {
                *(uint32_t*)&Cp[rA * ldc + gn] = pack2h(x0, x1);
                *(uint32_t*)&Cp[rB * ldc + gn] = pack2h(y0, y1);
            } else {
                *(float2*)(C + rA * ldc + gn) = make_float2(x0, x1);
                *(float2*)(C + rB * ldc + gn) = make_float2(y0, y1);
            }
        }
    }

    if (FLAGS & 32) {
        // deterministic per-tile column sums: smem [128 cols][16 contributors]
        float* scol = (float*)smem;           // reuse stage buffers (8 KB)
        const int contrib = (wid & 1) * 8 + (lane >> 2);
        __syncthreads();
#pragma unroll
        for (int nf = 0; nf < 4; nf++) {
            int cw = warpN + nf * 8 + (lane & 3) * 2;
            scol[(cw + 0) * 16 + contrib] = colsum[nf * 2];
            scol[(cw + 1) * 16 + contrib] = colsum[nf * 2 + 1];
        }
        __syncthreads();
        if (tid < 128) {
            float s = 0.f;
#pragma unroll
            for (int j = 0; j < 16; j++) s += scol[tid * 16 + j];
            g_tpart[(size_t)blockIdx.y * CH + n0 + tid] = s;
        }
    }
}

// ---------------- fold 4 tile sums per segment ----------------
__global__ void __launch_bounds__(256) segsum_k() {
    int idx = blockIdx.x * 256 + threadIdx.x;   // (b*8+seg)*4096 + c  (131072 total)
    int c = idx & 4095;
    int t0 = (idx >> 12) * 4;                   // first row-tile of segment
    float s = g_tpart[(size_t)t0 * CH + c]
            + g_tpart[(size_t)(t0 + 1) * CH + c]
            + g_tpart[(size_t)(t0 + 2) * CH + c]
            + g_tpart[(size_t)(t0 + 3) * CH + c];
    g_part[idx] = s;
}

// ---------------- conversion kernels ----------------
__global__ void __launch_bounds__(256) icvt_k(const float* __restrict__ src,
                                              uint16_t* __restrict__ p) {
    size_t i = (size_t)blockIdx.x * 256 + threadIdx.x;
    float4 v = ((const float4*)src)[i];
    ((uint2*)p)[i] = pack4h(v);
}

// W [K][N] fp32 -> single fp16 plane [N][K]
__global__ void __launch_bounds__(256) wsplit_k(const float* __restrict__ W,
                                                uint16_t* __restrict__ Tp,
                                                int K, int N) {
    __shared__ float tile[32][33];
    const int n0 = blockIdx.x * 32, k0 = blockIdx.y * 32;
    const float* Wp = W + (size_t)blockIdx.z * K * N;
    uint16_t* Hp = Tp + (size_t)blockIdx.z * K * N;
    int tx = threadIdx.x & 31, ty = threadIdx.x >> 5;
#pragma unroll
    for (int i = 0; i < 4; i++)
        tile[ty + 8 * i][tx] = Wp[(size_t)(k0 + ty + 8 * i) * N + n0 + tx];
    __syncthreads();
#pragma unroll
    for (int i = 0; i < 4; i++) {
        __half h = __float2half_rn(tile[tx][ty + 8 * i]);
        Hp[(size_t)(n0 + ty + 8 * i) * K + k0 + tx] = *(uint16_t*)&h;
    }
}

// ---------------- block reduce ----------------
__device__ __forceinline__ void block_reduce2(float& a, float& b) {
    __shared__ float sh[64];
    int lane = threadIdx.x & 31, wid = threadIdx.x >> 5;
#pragma unroll
    for (int o = 16; o > 0; o >>= 1) {
        a += __shfl_xor_sync(0xffffffffu, a, o);
        b += __shfl_xor_sync(0xffffffffu, b, o);
    }
    if (lane == 0) { sh[wid] = a; sh[32 + wid] = b; }
    __syncthreads();
    if (threadIdx.x < 32) {
        a = (lane < 8) ? sh[lane] : 0.f;
        b = (lane < 8) ? sh[32 + lane] : 0.f;
#pragma unroll
        for (int o = 4; o > 0; o >>= 1) {
            a += __shfl_xor_sync(0xffffffffu, a, o);
            b += __shfl_xor_sync(0xffffffffu, b, o);
        }
        if (lane == 0) { sh[0] = a; sh[32] = b; }
    }
    __syncthreads();
    a = sh[0]; b = sh[32];
}

// ---------------- segmented cumsum phase C (fp32, in place) ----------------
__global__ void __launch_bounds__(256) cumsumC_k() {
    int idx = blockIdx.x * 256 + threadIdx.x;
    int c = idx & 4095;
    int t = idx >> 12;
    int b = t >> 3, seg = t & 7;
    float* p = g_csum + ((size_t)b << 24) + (size_t)(seg * SEGL) * CH + c;
    float acc = 0.f;
    if (c < 2048) {
#pragma unroll
        for (int s2 = 0; s2 < NSEG; s2++)
            if (s2 < seg) acc += g_part[((b * NSEG + s2) << 12) + c];
#pragma unroll 8
        for (int i = 0; i < SEGL; i++) { acc += p[(size_t)i * CH]; p[(size_t)i * CH] = acc; }
    } else {
#pragma unroll
        for (int s2 = 0; s2 < NSEG; s2++)
            if (s2 > seg) acc += g_part[((b * NSEG + s2) << 12) + c];
#pragma unroll 8
        for (int i = SEGL - 1; i >= 0; i--) { acc += p[(size_t)i * CH]; p[(size_t)i * CH] = acc; }
    }
}

// ---------------- LN lc/rc -> cell plane + relu'd lci/rci (fp16) ----------------
__global__ void __launch_bounds__(256) ln_lcrc_k(
    const float* __restrict__ gl, const float* __restrict__ bl,
    const float* __restrict__ gr, const float* __restrict__ br_)
{
    const int row = blockIdx.x, side = blockIdx.y;
    const float4* x4 = (const float4*)(g_csum + (size_t)row * CH + side * 2048);
    float4 v[2];
    float s = 0.f, ss = 0.f;
#pragma unroll
    for (int k = 0; k < 2; k++) {
        v[k] = x4[threadIdx.x + k * 256];
        s  += v[k].x + v[k].y + v[k].z + v[k].w;
        ss += v[k].x * v[k].x + v[k].y * v[k].y + v[k].z * v[k].z + v[k].w * v[k].w;
    }
    block_reduce2(s, ss);
    float m  = s * (1.f / 2048.f);
    float rs = rsqrtf(ss * (1.f / 2048.f) - m * m + 1e-6f);

    const float4* g4 = (const float4*)(side ? gr  : gl);
    const float4* b4 = (const float4*)(side ? br_ : bl);
    uint16_t* ibuf = side ? rci16 : lci16;
#pragma unroll
    for (int k = 0; k < 2; k++) {
        int c4 = threadIdx.x + k * 256;
        int c  = c4 * 4;
        float4 gv = g4[c4], bv = b4[c4], xv = v[k];
        float4 o;
        o.x = (xv.x - m) * rs * gv.x + bv.x;
        o.y = (xv.y - m) * rs * gv.y + bv.y;
        o.z = (xv.z - m) * rs * gv.z + bv.z;
        o.w = (xv.w - m) * rs * gv.w + bv.w;
        if (c < 1024) {
            int h = c >> 7, ig = c & 127;
            size_t o16 = (size_t)row * (NHD * TGD) + h * TGD + side * 256 + ig;
            *(uint2*)&cell_p[o16] = pack4h(o);
        } else {
            o.x = fmaxf(o.x, 0.f); o.y = fmaxf(o.y, 0.f);
            o.z = fmaxf(o.z, 0.f); o.w = fmaxf(o.w, 0.f);
            *(uint2*)&ibuf[(size_t)row * ISZ + (c - 1024)] = pack4h(o);
        }
    }
}

// ---------------- LN gates + sigmoid (fp16 in place) ----------------
__global__ void __launch_bounds__(256) ln_g_k(const float* __restrict__ gg,
                                              const float* __restrict__ bg) {
    const int row = blockIdx.x;
    uint2* x2 = (uint2*)(gate16 + (size_t)row * (NHD * TGD));
    float4 v[3];
    float s = 0.f, ss = 0.f;
#pragma unroll
    for (int k = 0; k < 3; k++) {
        uint2 u = x2[threadIdx.x + k * 256];
        float2 a = unp2(u.x), b = unp2(u.y);
        v[k] = make_float4(a.x, a.y, b.x, b.y);
        s  += v[k].x + v[k].y + v[k].z + v[k].w;
        ss += v[k].x * v[k].x + v[k].y * v[k].y + v[k].z * v[k].z + v[k].w * v[k].w;
    }
    block_reduce2(s, ss);
    float m  = s * (1.f / 3072.f);
    float rs = rsqrtf(ss * (1.f / 3072.f) - m * m + 1e-6f);
    const float4* g4 = (const float4*)gg;
    const float4* b4 = (const float4*)bg;
#pragma unroll
    for (int k = 0; k < 3; k++) {
        int c4 = threadIdx.x + k * 256;
        float4 gv = g4[c4], bv = b4[c4], xv = v[k];
        float4 o;
        o.x = 1.f / (1.f + __expf(-((xv.x - m) * rs * gv.x + bv.x)));
        o.y = 1.f / (1.f + __expf(-((xv.y - m) * rs * gv.y + bv.y)));
        o.z = 1.f / (1.f + __expf(-((xv.z - m) * rs * gv.z + bv.z)));
        o.w = 1.f / (1.f + __expf(-((xv.w - m) * rs * gv.w + bv.w)));
        uint2 w;
        w.x = pack2h(o.x, o.y);
        w.y = pack2h(o.z, o.w);
        x2[c4] = w;
    }
}

// ---------------- LN ffn hidden (fp16 in) + relu -> hp plane ----------------
__global__ void __launch_bounds__(256) ln_f_k(const float* __restrict__ gf,
                                              const float* __restrict__ bf) {
    const int row = blockIdx.x;
    const uint2* x2 = (const uint2*)(hpre_p + (size_t)row * (NHD * FGD));
    float4 v[4];
    float s = 0.f, ss = 0.f;
#pragma unroll
    for (int k = 0; k < 4; k++) {
        uint2 u = x2[threadIdx.x + k * 256];
        float2 a = unp2(u.x), b = unp2(u.y);
        v[k] = make_float4(a.x, a.y, b.x, b.y);
        s  += v[k].x + v[k].y + v[k].z + v[k].w;
        ss += v[k].x * v[k].x + v[k].y * v[k].y + v[k].z * v[k].z + v[k].w * v[k].w;
    }
    block_reduce2(s, ss);
    float m  = s * (1.f / 4096.f);
    float rs = rsqrtf(ss * (1.f / 4096.f) - m * m + 1e-6f);
    const float4* g4 = (const float4*)gf;
    const float4* b4 = (const float4*)bf;
#pragma unroll
    for (int k = 0; k < 4; k++) {
        int c4 = threadIdx.x + k * 256;
        float4 gv = g4[c4], bv = b4[c4], xv = v[k];
        float4 o;
        o.x = fmaxf((xv.x - m) * rs * gv.x + bv.x, 0.f);
        o.y = fmaxf((xv.y - m) * rs * gv.y + bv.y, 0.f);
        o.z = fmaxf((xv.z - m) * rs * gv.z + bv.z, 0.f);
        o.w = fmaxf((xv.w - m) * rs * gv.w + bv.w, 0.f);
        *(uint2*)&hp_p[(size_t)row * (NHD * FGD) + c4 * 4] = pack4h(o);
    }
}

// ---------------- host ----------------
extern "C" void kernel_launch(void* const* d_in, const int* in_sizes, int n_in,
                              void* d_out, int out_size) {
    const float* inputs = (const float*)d_in[0];
    const unsigned char* mask = (const unsigned char*)d_in[1];
    const float* W_csum = (const float*)d_in[2];
    const float* b_csum = (const float*)d_in[3];
    const float* W_x    = (const float*)d_in[4];
    const float* b_x    = (const float*)d_in[5];
    const float* gl     = (const float*)d_in[6];
    const float* bel    = (const float*)d_in[7];
    const float* gr     = (const float*)d_in[8];
    const float* ber    = (const float*)d_in[9];
    const float* ggain  = (const float*)d_in[10];
    const float* beg    = (const float*)d_in[11];
    const float* gf     = (const float*)d_in[12];
    const float* bef    = (const float*)d_in[13];
    const float* W_g    = (const float*)d_in[14];
    const float* b_g    = (const float*)d_in[15];
    const float* W_f1   = (const float*)d_in[16];
    const float* b_f1   = (const float*)d_in[17];
    const float* W_f2   = (const float*)d_in[18];
    const float* b_f2   = (const float*)d_in[19];
    const float* W_o    = (const float*)d_in[20];
    const float* b_o    = (const float*)d_in[21];
    float* out = (float*)d_out;

    float* p_csum;
    cudaGetSymbolAddress((void**)&p_csum, g_csum);
    uint16_t *pg16, *pl16, *pr16;
    cudaGetSymbolAddress((void**)&pg16,  gate16);
    cudaGetSymbolAddress((void**)&pl16,  lci16);
    cudaGetSymbolAddress((void**)&pr16,  rci16);
    uint16_t *pis, *pcell, *phpre, *php, *ppre;
    uint16_t *pwcs, *pwx, *pwg, *pwf1, *pwf2, *pwo;
    cudaGetSymbolAddress((void**)&pis,   is_p);
    cudaGetSymbolAddress((void**)&pcell, cell_p);
    cudaGetSymbolAddress((void**)&phpre, hpre_p);
    cudaGetSymbolAddress((void**)&php,   hp_p);
    cudaGetSymbolAddress((void**)&ppre,  pre_p);
    cudaGetSymbolAddress((void**)&pwcs, wcs_p);
    cudaGetSymbolAddress((void**)&pwx,  wx_p);
    cudaGetSymbolAddress((void**)&pwg,  wg_p);
    cudaGetSymbolAddress((void**)&pwf1, wf1_p);
    cudaGetSymbolAddress((void**)&pwf2, wf2_p);
    cudaGetSymbolAddress((void**)&pwo,  wo_p);

    cudaFuncSetAttribute(hgemm_k<33>, cudaFuncAttributeMaxDynamicSharedMemorySize, SMT);
    cudaFuncSetAttribute(hgemm_k<2>,  cudaFuncAttributeMaxDynamicSharedMemorySize, SMT);
    cudaFuncSetAttribute(hgemm_k<4>,  cudaFuncAttributeMaxDynamicSharedMemorySize, SMT);
    cudaFuncSetAttribute(hgemm_k<8>,  cudaFuncAttributeMaxDynamicSharedMemorySize, SMT);
    cudaFuncSetAttribute(hgemm_k<16>, cudaFuncAttributeMaxDynamicSharedMemorySize, SMT);

    dim3 blk(256);

    // ---- conversions ----
    icvt_k<<<ROWS * ISZ / 1024, blk>>>(inputs, pis);
    wsplit_k<<<dim3(CH / 32, ISZ / 32, 1), blk>>>(W_csum, pwcs, ISZ, CH);
    wsplit_k<<<dim3(ISZ / 32, ISZ / 32, 1), blk>>>(W_x, pwx, ISZ, ISZ);
    wsplit_k<<<dim3(TGD / 32, TGD / 32, NHD), blk>>>(W_g, pwg, TGD, TGD);
    wsplit_k<<<dim3(FGD / 32, TGD / 32, NHD), blk>>>(W_f1, pwf1, TGD, FGD);
    wsplit_k<<<dim3(IGD / 32, FGD / 32, NHD), blk>>>(W_f2, pwf2, FGD, IGD);
    wsplit_k<<<dim3(ISZ / 32, ISZ / 32, 1), blk>>>(W_o, pwo, ISZ, ISZ);

    // 1) csum GEMM (masked, fp32 out) + per-tile column sums
    hgemm_k<33><<<dim3(CH / 128, ROWS / 128, 1), blk, SMT>>>(
        pis, ISZ, 0, pwcs, 0, b_csum, 0,
        p_csum, CH, 0, nullptr, CH, ISZ, mask, nullptr, nullptr, nullptr, nullptr);
    // 2) out_x GEMM -> cell plane (remap)
    hgemm_k<4><<<dim3(ISZ / 128, ROWS / 128, 1), blk, SMT>>>(
        pis, ISZ, 0, pwx, 0, b_x, 0,
        nullptr, NHD * TGD, 0, pcell, ISZ, ISZ, nullptr, nullptr, nullptr, nullptr, nullptr);
    // 3) fold tile sums -> segment sums (ALL 131072 entries); then scan
    segsum_k<<<512, 256>>>();
    cumsumC_k<<<512, 256>>>();
    // 4) LN lc/rc -> cell + fp16 lci/rci
    ln_lcrc_k<<<dim3(ROWS, 2), 256>>>(gl, bel, gr, ber);
    // 5) gates GEMM (fp16 out)
    hgemm_k<16><<<dim3(TGD / 128, ROWS / 128, NHD), blk, SMT>>>(
        pcell, NHD * TGD, TGD, pwg, (long)TGD * TGD, b_g, TGD,
        nullptr, NHD * TGD, TGD, pg16, TGD, TGD, nullptr, nullptr, nullptr, nullptr, nullptr);
    // 6) LN gates + sigmoid (fp16 in place)
    ln_g_k<<<ROWS, 256>>>(ggain, beg);
    // 7) ffn1 GEMM -> fp16 pre-LN hidden
    hgemm_k<16><<<dim3(FGD / 128, ROWS / 128, NHD), blk, SMT>>>(
        pcell, NHD * TGD, TGD, pwf1, (long)FGD * TGD, b_f1, FGD,
        nullptr, NHD * FGD, FGD, phpre, FGD, TGD, nullptr, nullptr, nullptr, nullptr, nullptr);
    // 8) LN ffn + relu -> hp plane
    ln_f_k<<<ROWS, 256>>>(gf, bef);
    // 9) ffn2 GEMM + fused combine -> pre plane
    hgemm_k<8><<<dim3(IGD / 128, ROWS / 128, NHD), blk, SMT>>>(
        php, NHD * FGD, FGD, pwf2, (long)IGD * FGD, b_f2, IGD,
        nullptr, ISZ, IGD, ppre, IGD, FGD, nullptr, nullptr, pg16, pl16, pr16);
    // 10) final GEMM + residual
    hgemm_k<2><<<dim3(ISZ / 128, ROWS / 128, 1), blk, SMT>>>(
        ppre, ISZ, 0, pwo, 0, b_o, 0,
        out, ISZ, 0, nullptr, ISZ, ISZ, nullptr, inputs, nullptr, nullptr, nullptr);
}

// round 15
// speedup vs baseline: 1.6672x; 1.0027x over previous
#include <cuda_runtime.h>
#include <cuda_fp16.h>
#include <cstdint>

#define ROWS 16384      // B*S
#define CH   4096
#define NHD  8
#define IGD  128
#define TGD  384
#define FGD  512
#define ISZ  1024
#define NSEG 8
#define SEGL 512        // 4096 / NSEG
#define NTILE (ROWS / 128)

// ---------------- scratch ----------------
__device__ float g_csum[(size_t)ROWS * CH];        // GEMM out + in-place scan (fp32)
__device__ float g_part[(size_t)4 * NSEG * CH];    // unused (kept for layout stability)
__device__ float g_tpart[(size_t)NTILE * CH];      // per-(row-tile,col) sums

__device__ __align__(16) uint16_t gate16[(size_t)ROWS * NHD * TGD];
__device__ __align__(16) uint16_t lci16 [(size_t)ROWS * ISZ];
__device__ __align__(16) uint16_t rci16 [(size_t)ROWS * ISZ];

// ---------------- activation planes: single fp16 ----------------
__device__ __align__(16) uint16_t is_p  [(size_t)ROWS * ISZ];
__device__ __align__(16) uint16_t cell_p[(size_t)ROWS * NHD * TGD];
__device__ __align__(16) uint16_t hpre_p[(size_t)ROWS * NHD * FGD];
__device__ __align__(16) uint16_t hp_p  [(size_t)ROWS * NHD * FGD];
__device__ __align__(16) uint16_t pre_p [(size_t)ROWS * ISZ];
// ---------------- weight planes: fp16, transposed [N][K]; combined ----------------
__device__ __align__(16) uint16_t wcsx [(size_t)(CH + ISZ) * ISZ];        // [5120][1024]
__device__ __align__(16) uint16_t wgf1 [(size_t)NHD * (TGD + FGD) * TGD]; // [8][896][384]
__device__ __align__(16) uint16_t wf2_p[(size_t)NHD * IGD * FGD];
__device__ __align__(16) uint16_t wo_p [(size_t)ISZ * ISZ];

// ---------------- helpers ----------------
__device__ __forceinline__ uint32_t smem_u32(const void* p) {
    uint32_t a;
    asm("{ .reg .u64 t; cvta.to.shared.u64 t, %1; cvt.u32.u64 %0, t; }" : "=r"(a) : "l"(p));
    return a;
}
#define CP16(dst, src) asm volatile("cp.async.cg.shared.global [%0], [%1], 16;" :: "r"(dst), "l"(src))
#define CP_COMMIT()    asm volatile("cp.async.commit_group;" ::: "memory")

__device__ __forceinline__ void ldm4(uint32_t& r0, uint32_t& r1, uint32_t& r2, uint32_t& r3, uint32_t a) {
    asm volatile("ldmatrix.sync.aligned.m8n8.x4.shared.b16 {%0,%1,%2,%3}, [%4];"
                 : "=r"(r0), "=r"(r1), "=r"(r2), "=r"(r3) : "r"(a));
}
__device__ __forceinline__ void mma16816(float* d, const uint32_t* a, const uint32_t* b) {
    asm volatile("mma.sync.aligned.m16n8k16.row.col.f32.f16.f16.f32 "
                 "{%0,%1,%2,%3},{%4,%5,%6,%7},{%8,%9},{%0,%1,%2,%3};"
                 : "+f"(d[0]), "+f"(d[1]), "+f"(d[2]), "+f"(d[3])
                 : "r"(a[0]), "r"(a[1]), "r"(a[2]), "r"(a[3]), "r"(b[0]), "r"(b[1]));
}
__device__ __forceinline__ uint32_t pack2h(float x, float y) {
    __half2 v = __floats2half2_rn(x, y);
    return *(uint32_t*)&v;
}
__device__ __forceinline__ uint2 pack4h(float4 v) {
    uint2 r;
    r.x = pack2h(v.x, v.y);
    r.y = pack2h(v.z, v.w);
    return r;
}
__device__ __forceinline__ float2 unp2(uint32_t u) { return __half22float2(*(__half2*)&u); }

// ---------------- fp16 tensor-core GEMM, double-buffered ----------------
// FLAGS: 2 residual fp32-out (final); 8 fused-combine (ffn2);
//        64 combined csum+out_x; 128 combined gates+ffn1
#define P_A  0
#define P_B  8192
#define STG  16384
#define SMT  32768

template <int FLAGS>
__global__ void __launch_bounds__(256, 2) hgemm_k(
    const uint16_t* __restrict__ Ap, int lda, int aoff,
    const uint16_t* __restrict__ Bp, long boff,
    const float* __restrict__ bias, int biasoff,
    float* __restrict__ C, int ldc, int coff,
    uint16_t* __restrict__ Cp,
    int N, int K,
    const unsigned char* __restrict__ mask,
    const float* __restrict__ resid,          // FLAG2: residual; FLAG64: b_x; FLAG128: b_f1
    const uint16_t* __restrict__ g16,
    const uint16_t* __restrict__ l16, const uint16_t* __restrict__ r16)
{
    extern __shared__ char smem[];
    const uint32_t sb = smem_u32(smem);
    const int tid = threadIdx.x, wid = tid >> 5, lane = tid & 31;
    const int z = blockIdx.z;

    Ap += (long)z * aoff;
    Bp += (long)z * boff;
    bias += (long)z * biasoff;
    C  += (long)z * coff;

    const int m0 = blockIdx.y * 128;
    const int n0 = blockIdx.x * 128;
    const int warpM = (wid & 1) * 64;
    const int warpN = (wid >> 1) * 32;

    const int rowA = warpM + (lane & 15);
    const int hiA  = (lane >> 4) & 1;
    const int swA  = (rowA >> 1) & 3;
    const uint32_t aRow = sb + P_A + (uint32_t)rowA * 64;

    const int rowB = warpN + (lane & 7) + ((lane & 16) >> 1);
    const int hiB  = (lane >> 3) & 1;
    const int swB  = (rowB >> 1) & 3;
    const uint32_t bRow = sb + P_B + (uint32_t)rowB * 64;

    const int su0 = tid, su1 = tid + 256;
    const int sr0 = su0 >> 2, sc0 = su0 & 3;
    const int sr1 = su1 >> 2, sc1 = su1 & 3;
    const uint32_t sd0 = (uint32_t)sr0 * 64 + ((uint32_t)(sc0 ^ ((sr0 >> 1) & 3)) << 4);
    const uint32_t sd1 = (uint32_t)sr1 * 64 + ((uint32_t)(sc1 ^ ((sr1 >> 1) & 3)) << 4);

    float acc[4][4][4];
#pragma unroll
    for (int i = 0; i < 4; i++)
#pragma unroll
        for (int j = 0; j < 4; j++)
#pragma unroll
            for (int q = 0; q < 4; q++) acc[i][j][q] = 0.f;

    const int nch = K >> 5;

#define STAGE(c, bs) do { \
        const int _k0 = (c) << 5; \
        const uint32_t _b = sb + (bs) * STG; \
        size_t _sa = (size_t)(m0 + sr0) * lda + _k0 + sc0 * 8; \
        CP16(_b + P_A + sd0, Ap + _sa); \
        size_t _sb2 = (size_t)(n0 + sr0) * K + _k0 + sc0 * 8; \
        CP16(_b + P_B + sd0, Bp + _sb2); \
        _sa = (size_t)(m0 + sr1) * lda + _k0 + sc1 * 8; \
        CP16(_b + P_A + sd1, Ap + _sa); \
        _sb2 = (size_t)(n0 + sr1) * K + _k0 + sc1 * 8; \
        CP16(_b + P_B + sd1, Bp + _sb2); \
        CP_COMMIT(); \
    } while (0)

    STAGE(0, 0);
    for (int c = 0; c < nch; c++) {
        const int bs = c & 1;
        if (c + 1 < nch) {
            STAGE(c + 1, bs ^ 1);
            asm volatile("cp.async.wait_group 1;" ::: "memory");
        } else {
            asm volatile("cp.async.wait_group 0;" ::: "memory");
        }
        __syncthreads();

        const uint32_t bb = (uint32_t)bs * STG;
#pragma unroll
        for (int ks = 0; ks < 2; ks++) {
            const uint32_t ca = ((uint32_t)((2 * ks + hiA) ^ swA)) << 4;
            const uint32_t cb = ((uint32_t)((2 * ks + hiB) ^ swB)) << 4;
            uint32_t bf[4][2];
            ldm4(bf[0][0], bf[0][1], bf[1][0], bf[1][1], bRow + bb + cb);
            ldm4(bf[2][0], bf[2][1], bf[3][0], bf[3][1], bRow + bb + 1024 + cb);
#pragma unroll
            for (int mf = 0; mf < 4; mf++) {
                uint32_t af[4];
                ldm4(af[0], af[1], af[2], af[3], aRow + bb + mf * 1024 + ca);
#pragma unroll
                for (int nf = 0; nf < 4; nf++)
                    mma16816(acc[mf][nf], af, bf[nf]);
            }
        }
        __syncthreads();
    }
#undef STAGE

    // ---------------- epilogue ----------------
    const bool iscs = (FLAGS & 64) ? (n0 < CH) : false;   // csum half of combined GEMM1
    const bool isg  = (FLAGS & 128) ? (n0 < TGD) : false; // gates half of combined GEMM2
    float colsum[8];
    if (FLAGS & 64) {
#pragma unroll
        for (int q = 0; q < 8; q++) colsum[q] = 0.f;
    }
#pragma unroll
    for (int mf = 0; mf < 4; mf++) {
        long rA = m0 + warpM + mf * 16 + (lane >> 2);
        long rB = rA + 8;
        float zfA = 1.f, zfB = 1.f;
        if (FLAGS & 64) {
            if (iscs) { zfA = mask[rA] ? 0.f : 1.f; zfB = mask[rB] ? 0.f : 1.f; }
        }
#pragma unroll
        for (int nf = 0; nf < 4; nf++) {
            int gn = n0 + warpN + nf * 8 + (lane & 3) * 2;
            float b0, b1;
            if (FLAGS & 64) {
                b0 = iscs ? bias[gn] : resid[gn - CH];
                b1 = iscs ? bias[gn + 1] : resid[gn - CH + 1];
            } else if (FLAGS & 128) {
                b0 = isg ? bias[gn] : resid[z * FGD + gn - TGD];
                b1 = isg ? bias[gn + 1] : resid[z * FGD + gn - TGD + 1];
            } else {
                b0 = bias[gn]; b1 = bias[gn + 1];
            }
            float x0 = acc[mf][nf][0] + b0, x1 = acc[mf][nf][1] + b1;
            float y0 = acc[mf][nf][2] + b0, y1 = acc[mf][nf][3] + b1;

            if (FLAGS & 64) {
                if (iscs) {
                    x0 *= zfA; x1 *= zfA; y0 *= zfB; y1 *= zfB;
                    colsum[nf * 2]     += x0 + y0;
                    colsum[nf * 2 + 1] += x1 + y1;
                    *(float2*)(g_csum + rA * CH + gn) = make_float2(x0, x1);
                    *(float2*)(g_csum + rB * CH + gn) = make_float2(y0, y1);
                } else {
                    int gx = gn - CH;
                    int cn = (gx >> 7) * TGD + IGD + (gx & 127);
                    *(uint32_t*)&cell_p[rA * (NHD * TGD) + cn] = pack2h(x0, x1);
                    *(uint32_t*)&cell_p[rB * (NHD * TGD) + cn] = pack2h(y0, y1);
                }
            } else if (FLAGS & 128) {
                if (isg) {
                    *(uint32_t*)&gate16[rA * (NHD * TGD) + z * TGD + gn] = pack2h(x0, x1);
                    *(uint32_t*)&gate16[rB * (NHD * TGD) + z * TGD + gn] = pack2h(y0, y1);
                } else {
                    int gx = gn - TGD;
                    *(uint32_t*)&hpre_p[rA * (NHD * FGD) + z * FGD + gx] = pack2h(x0, x1);
                    *(uint32_t*)&hpre_p[rB * (NHD * FGD) + z * FGD + gx] = pack2h(y0, y1);
                }
            } else if (FLAGS & 8) {
                int gc = z * IGD + gn;
                const uint16_t* gbA = g16 + rA * (NHD * TGD) + z * TGD;
                const uint16_t* gbB = g16 + rB * (NHD * TGD) + z * TGD;
                float2 lgA = unp2(*(const uint32_t*)&gbA[gn]);
                float2 igA = unp2(*(const uint32_t*)&gbA[IGD + gn]);
                float2 rgA = unp2(*(const uint32_t*)&gbA[2 * IGD + gn]);
                float2 lgB = unp2(*(const uint32_t*)&gbB[gn]);
                float2 igB = unp2(*(const uint32_t*)&gbB[IGD + gn]);
                float2 rgB = unp2(*(const uint32_t*)&gbB[2 * IGD + gn]);
                float2 liA = unp2(*(const uint32_t*)&l16[rA * ISZ + gc]);
                float2 riA = unp2(*(const uint32_t*)&r16[rA * ISZ + gc]);
                float2 liB = unp2(*(const uint32_t*)&l16[rB * ISZ + gc]);
                float2 riB = unp2(*(const uint32_t*)&r16[rB * ISZ + gc]);
                float o0 = liA.x * lgA.x + igA.x * x0 + riA.x * rgA.x;
                float o1 = liA.y * lgA.y + igA.y * x1 + riA.y * rgA.y;
                float o2 = liB.x * lgB.x + igB.x * y0 + riB.x * rgB.x;
                float o3 = liB.y * lgB.y + igB.y * y1 + riB.y * rgB.y;
                *(uint32_t*)&pre_p[rA * ISZ + gc] = pack2h(o0, o1);
                *(uint32_t*)&pre_p[rB * ISZ + gc] = pack2h(o2, o3);
            } else { // FLAG2 final
                x0 += resid[rA * N + gn]; x1 += resid[rA * N + gn + 1];
                y0 += resid[rB * N + gn]; y1 += resid[rB * N + gn + 1];
                *(float2*)(C + rA * ldc + gn) = make_float2(x0, x1);
                *(float2*)(C + rB * ldc + gn) = make_float2(y0, y1);
            }
        }
    }

    if ((FLAGS & 64) && iscs) {
        float* scol = (float*)smem;
        const int contrib = (wid & 1) * 8 + (lane >> 2);
        __syncthreads();
#pragma unroll
        for (int nf = 0; nf < 4; nf++) {
            int cw = warpN + nf * 8 + (lane & 3) * 2;
            scol[(cw + 0) * 16 + contrib] = colsum[nf * 2];
            scol[(cw + 1) * 16 + contrib] = colsum[nf * 2 + 1];
        }
        __syncthreads();
        if (tid < 128) {
            float s = 0.f;
#pragma unroll
            for (int j = 0; j < 16; j++) s += scol[tid * 16 + j];
            g_tpart[(size_t)blockIdx.y * CH + n0 + tid] = s;
        }
    }
}

// ---------------- conversion kernels ----------------
__global__ void __launch_bounds__(256) icvt_k(const float* __restrict__ src,
                                              uint16_t* __restrict__ p) {
    size_t i = (size_t)blockIdx.x * 256 + threadIdx.x;
    float4 v = ((const float4*)src)[i];
    ((uint2*)p)[i] = pack4h(v);
}

// W [K][N] fp32 (per z: stride K*N) -> fp16 plane [N][K] at Tp + z*dzs
__global__ void __launch_bounds__(256) wsplit_k(const float* __restrict__ W,
                                                uint16_t* __restrict__ Tp,
                                                int K, int N, long dzs) {
    __shared__ float tile[32][33];
    const int n0 = blockIdx.x * 32, k0 = blockIdx.y * 32;
    const float* Wp = W + (size_t)blockIdx.z * K * N;
    uint16_t* Hp = Tp + (size_t)blockIdx.z * dzs;
    int tx = threadIdx.x & 31, ty = threadIdx.x >> 5;
#pragma unroll
    for (int i = 0; i < 4; i++)
        tile[ty + 8 * i][tx] = Wp[(size_t)(k0 + ty + 8 * i) * N + n0 + tx];
    __syncthreads();
#pragma unroll
    for (int i = 0; i < 4; i++) {
        __half h = __float2half_rn(tile[tx][ty + 8 * i]);
        Hp[(size_t)(n0 + ty + 8 * i) * K + k0 + tx] = *(uint16_t*)&h;
    }
}

// ---------------- block reduce ----------------
__device__ __forceinline__ void block_reduce2(float& a, float& b) {
    __shared__ float sh[64];
    int lane = threadIdx.x & 31, wid = threadIdx.x >> 5;
#pragma unroll
    for (int o = 16; o > 0; o >>= 1) {
        a += __shfl_xor_sync(0xffffffffu, a, o);
        b += __shfl_xor_sync(0xffffffffu, b, o);
    }
    if (lane == 0) { sh[wid] = a; sh[32 + wid] = b; }
    __syncthreads();
    if (threadIdx.x < 32) {
        a = (lane < 8) ? sh[lane] : 0.f;
        b = (lane < 8) ? sh[32 + lane] : 0.f;
#pragma unroll
        for (int o = 4; o > 0; o >>= 1) {
            a += __shfl_xor_sync(0xffffffffu, a, o);
            b += __shfl_xor_sync(0xffffffffu, b, o);
        }
        if (lane == 0) { sh[0] = a; sh[32] = b; }
    }
    __syncthreads();
    a = sh[0]; b = sh[32];
}

// ---------------- segmented cumsum (fp32, in place; tile sums inlined) ----------------
__global__ void __launch_bounds__(256) cumsumC_k() {
    int idx = blockIdx.x * 256 + threadIdx.x;
    int c = idx & 4095;
    int t = idx >> 12;
    int b = t >> 3, seg = t & 7;
    float* p = g_csum + ((size_t)b << 24) + (size_t)(seg * SEGL) * CH + c;
    float acc = 0.f;
    if (c < 2048) {
#pragma unroll
        for (int s2 = 0; s2 < NSEG; s2++)
            if (s2 < seg) {
                int t0 = (b * NSEG + s2) * 4;
                acc += g_tpart[(size_t)t0 * CH + c] + g_tpart[(size_t)(t0 + 1) * CH + c]
                     + g_tpart[(size_t)(t0 + 2) * CH + c] + g_tpart[(size_t)(t0 + 3) * CH + c];
            }
#pragma unroll 8
        for (int i = 0; i < SEGL; i++) { acc += p[(size_t)i * CH]; p[(size_t)i * CH] = acc; }
    } else {
#pragma unroll
        for (int s2 = 0; s2 < NSEG; s2++)
            if (s2 > seg) {
                int t0 = (b * NSEG + s2) * 4;
                acc += g_tpart[(size_t)t0 * CH + c] + g_tpart[(size_t)(t0 + 1) * CH + c]
                     + g_tpart[(size_t)(t0 + 2) * CH + c] + g_tpart[(size_t)(t0 + 3) * CH + c];
            }
#pragma unroll 8
        for (int i = SEGL - 1; i >= 0; i--) { acc += p[(size_t)i * CH]; p[(size_t)i * CH] = acc; }
    }
}

// ---------------- LN lc/rc -> cell plane + relu'd lci/rci (fp16) ----------------
__global__ void __launch_bounds__(256) ln_lcrc_k(
    const float* __restrict__ gl, const float* __restrict__ bl,
    const float* __restrict__ gr, const float* __restrict__ br_)
{
    const int row = blockIdx.x, side = blockIdx.y;
    const float4* x4 = (const float4*)(g_csum + (size_t)row * CH + side * 2048);
    float4 v[2];
    float s = 0.f, ss = 0.f;
#pragma unroll
    for (int k = 0; k < 2; k++) {
        v[k] = x4[threadIdx.x + k * 256];
        s  += v[k].x + v[k].y + v[k].z + v[k].w;
        ss += v[k].x * v[k].x + v[k].y * v[k].y + v[k].z * v[k].z + v[k].w * v[k].w;
    }
    block_reduce2(s, ss);
    float m  = s * (1.f / 2048.f);
    float rs = rsqrtf(ss * (1.f / 2048.f) - m * m + 1e-6f);

    const float4* g4 = (const float4*)(side ? gr  : gl);
    const float4* b4 = (const float4*)(side ? br_ : bl);
    uint16_t* ibuf = side ? rci16 : lci16;
#pragma unroll
    for (int k = 0; k < 2; k++) {
        int c4 = threadIdx.x + k * 256;
        int c  = c4 * 4;
        float4 gv = g4[c4], bv = b4[c4], xv = v[k];
        float4 o;
        o.x = (xv.x - m) * rs * gv.x + bv.x;
        o.y = (xv.y - m) * rs * gv.y + bv.y;
        o.z = (xv.z - m) * rs * gv.z + bv.z;
        o.w = (xv.w - m) * rs * gv.w + bv.w;
        if (c < 1024) {
            int h = c >> 7, ig = c & 127;
            size_t o16 = (size_t)row * (NHD * TGD) + h * TGD + side * 256 + ig;
            *(uint2*)&cell_p[o16] = pack4h(o);
        } else {
            o.x = fmaxf(o.x, 0.f); o.y = fmaxf(o.y, 0.f);
            o.z = fmaxf(o.z, 0.f); o.w = fmaxf(o.w, 0.f);
            *(uint2*)&ibuf[(size_t)row * ISZ + (c - 1024)] = pack4h(o);
        }
    }
}

// ---------------- merged LN: y==0 gates+sigmoid (in place); y==1 ffn+relu ----------------
__global__ void __launch_bounds__(256) ln_gf_k(
    const float* __restrict__ gg, const float* __restrict__ bg,
    const float* __restrict__ gf, const float* __restrict__ bf)
{
    const int row = blockIdx.x;
    if (blockIdx.y == 0) {
        uint2* x2 = (uint2*)(gate16 + (size_t)row * (NHD * TGD));
        float4 v[3];
        float s = 0.f, ss = 0.f;
#pragma unroll
        for (int k = 0; k < 3; k++) {
            uint2 u = x2[threadIdx.x + k * 256];
            float2 a = unp2(u.x), b = unp2(u.y);
            v[k] = make_float4(a.x, a.y, b.x, b.y);
            s  += v[k].x + v[k].y + v[k].z + v[k].w;
            ss += v[k].x * v[k].x + v[k].y * v[k].y + v[k].z * v[k].z + v[k].w * v[k].w;
        }
        block_reduce2(s, ss);
        float m  = s * (1.f / 3072.f);
        float rs = rsqrtf(ss * (1.f / 3072.f) - m * m + 1e-6f);
        const float4* g4 = (const float4*)gg;
        const float4* b4 = (const float4*)bg;
#pragma unroll
        for (int k = 0; k < 3; k++) {
            int c4 = threadIdx.x + k * 256;
            float4 gv = g4[c4], bv = b4[c4], xv = v[k];
            float4 o;
            o.x = 1.f / (1.f + __expf(-((xv.x - m) * rs * gv.x + bv.x)));
            o.y = 1.f / (1.f + __expf(-((xv.y - m) * rs * gv.y + bv.y)));
            o.z = 1.f / (1.f + __expf(-((xv.z - m) * rs * gv.z + bv.z)));
            o.w = 1.f / (1.f + __expf(-((xv.w - m) * rs * gv.w + bv.w)));
            uint2 w;
            w.x = pack2h(o.x, o.y);
            w.y = pack2h(o.z, o.w);
            x2[c4] = w;
        }
    } else {
        const uint2* x2 = (const uint2*)(hpre_p + (size_t)row * (NHD * FGD));
        float4 v[4];
        float s = 0.f, ss = 0.f;
#pragma unroll
        for (int k = 0; k < 4; k++) {
            uint2 u = x2[threadIdx.x + k * 256];
            float2 a = unp2(u.x), b = unp2(u.y);
            v[k] = make_float4(a.x, a.y, b.x, b.y);
            s  += v[k].x + v[k].y + v[k].z + v[k].w;
            ss += v[k].x * v[k].x + v[k].y * v[k].y + v[k].z * v[k].z + v[k].w * v[k].w;
        }
        block_reduce2(s, ss);
        float m  = s * (1.f / 4096.f);
        float rs = rsqrtf(ss * (1.f / 4096.f) - m * m + 1e-6f);
        const float4* g4 = (const float4*)gf;
        const float4* b4 = (const float4*)bf;
#pragma unroll
        for (int k = 0; k < 4; k++) {
            int c4 = threadIdx.x + k * 256;
            float4 gv = g4[c4], bv = b4[c4], xv = v[k];
            float4 o;
            o.x = fmaxf((xv.x - m) * rs * gv.x + bv.x, 0.f);
            o.y = fmaxf((xv.y - m) * rs * gv.y + bv.y, 0.f);
            o.z = fmaxf((xv.z - m) * rs * gv.z + bv.z, 0.f);
            o.w = fmaxf((xv.w - m) * rs * gv.w + bv.w, 0.f);
            *(uint2*)&hp_p[(size_t)row * (NHD * FGD) + c4 * 4] = pack4h(o);
        }
    }
}

// ---------------- host ----------------
extern "C" void kernel_launch(void* const* d_in, const int* in_sizes, int n_in,
                              void* d_out, int out_size) {
    const float* inputs = (const float*)d_in[0];
    const unsigned char* mask = (const unsigned char*)d_in[1];
    const float* W_csum = (const float*)d_in[2];
    const float* b_csum = (const float*)d_in[3];
    const float* W_x    = (const float*)d_in[4];
    const float* b_x    = (const float*)d_in[5];
    const float* gl     = (const float*)d_in[6];
    const float* bel    = (const float*)d_in[7];
    const float* gr     = (const float*)d_in[8];
    const float* ber    = (const float*)d_in[9];
    const float* ggain  = (const float*)d_in[10];
    const float* beg    = (const float*)d_in[11];
    const float* gf     = (const float*)d_in[12];
    const float* bef    = (const float*)d_in[13];
    const float* W_g    = (const float*)d_in[14];
    const float* b_g    = (const float*)d_in[15];
    const float* W_f1   = (const float*)d_in[16];
    const float* b_f1   = (const float*)d_in[17];
    const float* W_f2   = (const float*)d_in[18];
    const float* b_f2   = (const float*)d_in[19];
    const float* W_o    = (const float*)d_in[20];
    const float* b_o    = (const float*)d_in[21];
    float* out = (float*)d_out;

    uint16_t *pg16, *pl16, *pr16;
    cudaGetSymbolAddress((void**)&pg16,  gate16);
    cudaGetSymbolAddress((void**)&pl16,  lci16);
    cudaGetSymbolAddress((void**)&pr16,  rci16);
    uint16_t *pis, *pcell, *php, *ppre;
    uint16_t *pwcsx, *pwgf1, *pwf2, *pwo;
    cudaGetSymbolAddress((void**)&pis,   is_p);
    cudaGetSymbolAddress((void**)&pcell, cell_p);
    cudaGetSymbolAddress((void**)&php,   hp_p);
    cudaGetSymbolAddress((void**)&ppre,  pre_p);
    cudaGetSymbolAddress((void**)&pwcsx, wcsx);
    cudaGetSymbolAddress((void**)&pwgf1, wgf1);
    cudaGetSymbolAddress((void**)&pwf2,  wf2_p);
    cudaGetSymbolAddress((void**)&pwo,   wo_p);

    cudaFuncSetAttribute(hgemm_k<64>,  cudaFuncAttributeMaxDynamicSharedMemorySize, SMT);
    cudaFuncSetAttribute(hgemm_k<128>, cudaFuncAttributeMaxDynamicSharedMemorySize, SMT);
    cudaFuncSetAttribute(hgemm_k<8>,   cudaFuncAttributeMaxDynamicSharedMemorySize, SMT);
    cudaFuncSetAttribute(hgemm_k<2>,   cudaFuncAttributeMaxDynamicSharedMemorySize, SMT);

    dim3 blk(256);

    // ---- conversions ----
    icvt_k<<<ROWS * ISZ / 1024, blk>>>(inputs, pis);
    wsplit_k<<<dim3(CH / 32, ISZ / 32, 1), blk>>>(W_csum, pwcsx, ISZ, CH, 0);
    wsplit_k<<<dim3(ISZ / 32, ISZ / 32, 1), blk>>>(W_x, pwcsx + (size_t)CH * ISZ, ISZ, ISZ, 0);
    wsplit_k<<<dim3(TGD / 32, TGD / 32, NHD), blk>>>(W_g, pwgf1, TGD, TGD, (long)(TGD + FGD) * TGD);
    wsplit_k<<<dim3(FGD / 32, TGD / 32, NHD), blk>>>(W_f1, pwgf1 + (size_t)TGD * TGD, TGD, FGD, (long)(TGD + FGD) * TGD);
    wsplit_k<<<dim3(IGD / 32, FGD / 32, NHD), blk>>>(W_f2, pwf2, FGD, IGD, (long)IGD * FGD);
    wsplit_k<<<dim3(ISZ / 32, ISZ / 32, 1), blk>>>(W_o, pwo, ISZ, ISZ, 0);

    // 1) combined csum + out_x GEMM (N = 5120)
    hgemm_k<64><<<dim3((CH + ISZ) / 128, ROWS / 128, 1), blk, SMT>>>(
        pis, ISZ, 0, pwcsx, 0, b_csum, 0,
        nullptr, CH, 0, nullptr, CH + ISZ, ISZ, mask, b_x, nullptr, nullptr, nullptr);
    // 2) segmented scan (tile sums inlined)
    cumsumC_k<<<512, 256>>>();
    // 3) LN lc/rc -> cell + fp16 lci/rci
    ln_lcrc_k<<<dim3(ROWS, 2), 256>>>(gl, bel, gr, ber);
    // 4) combined gates + ffn1 GEMM (N = 896 per head)
    hgemm_k<128><<<dim3((TGD + FGD) / 128, ROWS / 128, NHD), blk, SMT>>>(
        pcell, NHD * TGD, TGD, pwgf1, (long)(TGD + FGD) * TGD, b_g, TGD,
        nullptr, 0, 0, nullptr, TGD + FGD, TGD, nullptr, b_f1, nullptr, nullptr, nullptr);
    // 5) merged LN gates+sigmoid / LN ffn+relu
    ln_gf_k<<<dim3(ROWS, 2), 256>>>(ggain, beg, gf, bef);
    // 6) ffn2 GEMM + fused combine -> pre plane
    hgemm_k<8><<<dim3(IGD / 128, ROWS / 128, NHD), blk, SMT>>>(
        php, NHD * FGD, FGD, pwf2, (long)IGD * FGD, b_f2, IGD,
        nullptr, ISZ, IGD, nullptr, IGD, FGD, nullptr, nullptr, pg16, pl16, pr16);
    // 7) final GEMM + residual
    hgemm_k<2><<<dim3(ISZ / 128, ROWS / 128, 1), blk, SMT>>>(
        ppre, ISZ, 0, pwo, 0, b_o, 0,
        out, ISZ, 0, nullptr, ISZ, ISZ, nullptr, inputs, nullptr, nullptr, nullptr);
}

// round 16
// speedup vs baseline: 1.6817x; 1.0087x over previous
#include <cuda_runtime.h>
#include <cuda_fp16.h>
#include <cstdint>

#define ROWS 16384      // B*S
#define CH   4096
#define NHD  8
#define IGD  128
#define TGD  384
#define FGD  512
#define ISZ  1024
#define NSEG 8
#define SEGL 512
#define NTILE (ROWS / 128)

// ---------------- scratch ----------------
__device__ float g_csum[(size_t)ROWS * CH];
__device__ float g_tpart[(size_t)NTILE * CH];

__device__ __align__(16) uint16_t gate16[(size_t)ROWS * NHD * TGD];
__device__ __align__(16) uint16_t lci16 [(size_t)ROWS * ISZ];
__device__ __align__(16) uint16_t rci16 [(size_t)ROWS * ISZ];

// ---------------- activation planes: single fp16 ----------------
__device__ __align__(16) uint16_t is_p  [(size_t)ROWS * ISZ];
__device__ __align__(16) uint16_t cell_p[(size_t)ROWS * NHD * TGD];
__device__ __align__(16) uint16_t hpre_p[(size_t)ROWS * NHD * FGD];
__device__ __align__(16) uint16_t hp_p  [(size_t)ROWS * NHD * FGD];
__device__ __align__(16) uint16_t pre_p [(size_t)ROWS * ISZ];
// ---------------- weight planes: fp16, transposed [N][K]; combined ----------------
__device__ __align__(16) uint16_t wcsx [(size_t)(CH + ISZ) * ISZ];
__device__ __align__(16) uint16_t wgf1 [(size_t)NHD * (TGD + FGD) * TGD];
__device__ __align__(16) uint16_t wf2_p[(size_t)NHD * IGD * FGD];
__device__ __align__(16) uint16_t wo_p [(size_t)ISZ * ISZ];

// ---------------- helpers ----------------
__device__ __forceinline__ uint32_t smem_u32(const void* p) {
    uint32_t a;
    asm("{ .reg .u64 t; cvta.to.shared.u64 t, %1; cvt.u32.u64 %0, t; }" : "=r"(a) : "l"(p));
    return a;
}
#define CP16(dst, src) asm volatile("cp.async.cg.shared.global [%0], [%1], 16;" :: "r"(dst), "l"(src))
#define CP_COMMIT()    asm volatile("cp.async.commit_group;" ::: "memory")

__device__ __forceinline__ void ldm4(uint32_t& r0, uint32_t& r1, uint32_t& r2, uint32_t& r3, uint32_t a) {
    asm volatile("ldmatrix.sync.aligned.m8n8.x4.shared.b16 {%0,%1,%2,%3}, [%4];"
                 : "=r"(r0), "=r"(r1), "=r"(r2), "=r"(r3) : "r"(a));
}
__device__ __forceinline__ void mma16816(float* d, const uint32_t* a, const uint32_t* b) {
    asm volatile("mma.sync.aligned.m16n8k16.row.col.f32.f16.f16.f32 "
                 "{%0,%1,%2,%3},{%4,%5,%6,%7},{%8,%9},{%0,%1,%2,%3};"
                 : "+f"(d[0]), "+f"(d[1]), "+f"(d[2]), "+f"(d[3])
                 : "r"(a[0]), "r"(a[1]), "r"(a[2]), "r"(a[3]), "r"(b[0]), "r"(b[1]));
}
__device__ __forceinline__ uint32_t pack2h(float x, float y) {
    __half2 v = __floats2half2_rn(x, y);
    return *(uint32_t*)&v;
}
__device__ __forceinline__ uint2 pack4h(float4 v) {
    uint2 r;
    r.x = pack2h(v.x, v.y);
    r.y = pack2h(v.z, v.w);
    return r;
}
__device__ __forceinline__ float2 unp2(uint32_t u) { return __half22float2(*(__half2*)&u); }

// ---------------- fp16 tensor-core GEMM, double-buffered ----------------
// FLAGS: 2 residual fp32-out (final); 8 fused-combine (ffn2);
//        64 combined csum+out_x; 128 combined gates+ffn1
#define P_A  0
#define P_B  8192
#define STG  16384
#define SMT  32768

template <int FLAGS>
__global__ void __launch_bounds__(256, 2) hgemm_k(
    const uint16_t* __restrict__ Ap, int lda, int aoff,
    const uint16_t* __restrict__ Bp, long boff,
    const float* __restrict__ bias, int biasoff,
    float* __restrict__ C, int ldc, int coff,
    uint16_t* __restrict__ Cp,
    int N, int K,
    const unsigned char* __restrict__ mask,
    const float* __restrict__ resid,          // FLAG2: residual; FLAG64: b_x; FLAG128: b_f1
    const uint16_t* __restrict__ g16,
    const uint16_t* __restrict__ l16, const uint16_t* __restrict__ r16)
{
    extern __shared__ char smem[];
    const uint32_t sb = smem_u32(smem);
    const int tid = threadIdx.x, wid = tid >> 5, lane = tid & 31;
    const int z = blockIdx.z;

    Ap += (long)z * aoff;
    Bp += (long)z * boff;
    bias += (long)z * biasoff;
    C  += (long)z * coff;

    const int m0 = blockIdx.y * 128;
    const int n0 = blockIdx.x * 128;
    const int warpM = (wid & 1) * 64;
    const int warpN = (wid >> 1) * 32;

    const int rowA = warpM + (lane & 15);
    const int hiA  = (lane >> 4) & 1;
    const int swA  = (rowA >> 1) & 3;
    const uint32_t aRow = sb + P_A + (uint32_t)rowA * 64;

    const int rowB = warpN + (lane & 7) + ((lane & 16) >> 1);
    const int hiB  = (lane >> 3) & 1;
    const int swB  = (rowB >> 1) & 3;
    const uint32_t bRow = sb + P_B + (uint32_t)rowB * 64;

    const int su0 = tid, su1 = tid + 256;
    const int sr0 = su0 >> 2, sc0 = su0 & 3;
    const int sr1 = su1 >> 2, sc1 = su1 & 3;
    const uint32_t sd0 = (uint32_t)sr0 * 64 + ((uint32_t)(sc0 ^ ((sr0 >> 1) & 3)) << 4);
    const uint32_t sd1 = (uint32_t)sr1 * 64 + ((uint32_t)(sc1 ^ ((sr1 >> 1) & 3)) << 4);

    float acc[4][4][4];
#pragma unroll
    for (int i = 0; i < 4; i++)
#pragma unroll
        for (int j = 0; j < 4; j++)
#pragma unroll
            for (int q = 0; q < 4; q++) acc[i][j][q] = 0.f;

    const int nch = K >> 5;

#define STAGE(c, bs) do { \
        const int _k0 = (c) << 5; \
        const uint32_t _b = sb + (bs) * STG; \
        size_t _sa = (size_t)(m0 + sr0) * lda + _k0 + sc0 * 8; \
        CP16(_b + P_A + sd0, Ap + _sa); \
        size_t _sb2 = (size_t)(n0 + sr0) * K + _k0 + sc0 * 8; \
        CP16(_b + P_B + sd0, Bp + _sb2); \
        _sa = (size_t)(m0 + sr1) * lda + _k0 + sc1 * 8; \
        CP16(_b + P_A + sd1, Ap + _sa); \
        _sb2 = (size_t)(n0 + sr1) * K + _k0 + sc1 * 8; \
        CP16(_b + P_B + sd1, Bp + _sb2); \
        CP_COMMIT(); \
    } while (0)

    STAGE(0, 0);
    for (int c = 0; c < nch; c++) {
        const int bs = c & 1;
        if (c + 1 < nch) {
            STAGE(c + 1, bs ^ 1);
            asm volatile("cp.async.wait_group 1;" ::: "memory");
        } else {
            asm volatile("cp.async.wait_group 0;" ::: "memory");
        }
        __syncthreads();

        const uint32_t bb = (uint32_t)bs * STG;
#pragma unroll
        for (int ks = 0; ks < 2; ks++) {
            const uint32_t ca = ((uint32_t)((2 * ks + hiA) ^ swA)) << 4;
            const uint32_t cb = ((uint32_t)((2 * ks + hiB) ^ swB)) << 4;
            uint32_t bf[4][2];
            ldm4(bf[0][0], bf[0][1], bf[1][0], bf[1][1], bRow + bb + cb);
            ldm4(bf[2][0], bf[2][1], bf[3][0], bf[3][1], bRow + bb + 1024 + cb);
#pragma unroll
            for (int mf = 0; mf < 4; mf++) {
                uint32_t af[4];
                ldm4(af[0], af[1], af[2], af[3], aRow + bb + mf * 1024 + ca);
#pragma unroll
                for (int nf = 0; nf < 4; nf++)
                    mma16816(acc[mf][nf], af, bf[nf]);
            }
        }
        __syncthreads();
    }
#undef STAGE

    // ---------------- epilogue ----------------
    const bool iscs = (FLAGS & 64) ? (n0 < CH) : false;
    const bool isg  = (FLAGS & 128) ? (n0 < TGD) : false;
    float colsum[8];
    if (FLAGS & 64) {
#pragma unroll
        for (int q = 0; q < 8; q++) colsum[q] = 0.f;
    }
#pragma unroll
    for (int mf = 0; mf < 4; mf++) {
        long rA = m0 + warpM + mf * 16 + (lane >> 2);
        long rB = rA + 8;
        float zfA = 1.f, zfB = 1.f;
        if (FLAGS & 64) {
            if (iscs) { zfA = mask[rA] ? 0.f : 1.f; zfB = mask[rB] ? 0.f : 1.f; }
        }
#pragma unroll
        for (int nf = 0; nf < 4; nf++) {
            int gn = n0 + warpN + nf * 8 + (lane & 3) * 2;
            float b0, b1;
            if (FLAGS & 64) {
                b0 = iscs ? bias[gn] : resid[gn - CH];
                b1 = iscs ? bias[gn + 1] : resid[gn - CH + 1];
            } else if (FLAGS & 128) {
                b0 = isg ? bias[gn] : resid[z * FGD + gn - TGD];
                b1 = isg ? bias[gn + 1] : resid[z * FGD + gn - TGD + 1];
            } else {
                b0 = bias[gn]; b1 = bias[gn + 1];
            }
            float x0 = acc[mf][nf][0] + b0, x1 = acc[mf][nf][1] + b1;
            float y0 = acc[mf][nf][2] + b0, y1 = acc[mf][nf][3] + b1;

            if (FLAGS & 64) {
                if (iscs) {
                    x0 *= zfA; x1 *= zfA; y0 *= zfB; y1 *= zfB;
                    colsum[nf * 2]     += x0 + y0;
                    colsum[nf * 2 + 1] += x1 + y1;
                    *(float2*)(g_csum + rA * CH + gn) = make_float2(x0, x1);
                    *(float2*)(g_csum + rB * CH + gn) = make_float2(y0, y1);
                } else {
                    int gx = gn - CH;
                    int cn = (gx >> 7) * TGD + IGD + (gx & 127);
                    *(uint32_t*)&cell_p[rA * (NHD * TGD) + cn] = pack2h(x0, x1);
                    *(uint32_t*)&cell_p[rB * (NHD * TGD) + cn] = pack2h(y0, y1);
                }
            } else if (FLAGS & 128) {
                if (isg) {
                    *(uint32_t*)&gate16[rA * (NHD * TGD) + z * TGD + gn] = pack2h(x0, x1);
                    *(uint32_t*)&gate16[rB * (NHD * TGD) + z * TGD + gn] = pack2h(y0, y1);
                } else {
                    int gx = gn - TGD;
                    *(uint32_t*)&hpre_p[rA * (NHD * FGD) + z * FGD + gx] = pack2h(x0, x1);
                    *(uint32_t*)&hpre_p[rB * (NHD * FGD) + z * FGD + gx] = pack2h(y0, y1);
                }
            } else if (FLAGS & 8) {
                int gc = z * IGD + gn;
                const uint16_t* gbA = g16 + rA * (NHD * TGD) + z * TGD;
                const uint16_t* gbB = g16 + rB * (NHD * TGD) + z * TGD;
                float2 lgA = unp2(*(const uint32_t*)&gbA[gn]);
                float2 igA = unp2(*(const uint32_t*)&gbA[IGD + gn]);
                float2 rgA = unp2(*(const uint32_t*)&gbA[2 * IGD + gn]);
                float2 lgB = unp2(*(const uint32_t*)&gbB[gn]);
                float2 igB = unp2(*(const uint32_t*)&gbB[IGD + gn]);
                float2 rgB = unp2(*(const uint32_t*)&gbB[2 * IGD + gn]);
                float2 liA = unp2(*(const uint32_t*)&l16[rA * ISZ + gc]);
                float2 riA = unp2(*(const uint32_t*)&r16[rA * ISZ + gc]);
                float2 liB = unp2(*(const uint32_t*)&l16[rB * ISZ + gc]);
                float2 riB = unp2(*(const uint32_t*)&r16[rB * ISZ + gc]);
                float o0 = liA.x * lgA.x + igA.x * x0 + riA.x * rgA.x;
                float o1 = liA.y * lgA.y + igA.y * x1 + riA.y * rgA.y;
                float o2 = liB.x * lgB.x + igB.x * y0 + riB.x * rgB.x;
                float o3 = liB.y * lgB.y + igB.y * y1 + riB.y * rgB.y;
                *(uint32_t*)&pre_p[rA * ISZ + gc] = pack2h(o0, o1);
                *(uint32_t*)&pre_p[rB * ISZ + gc] = pack2h(o2, o3);
            } else {
                x0 += resid[rA * N + gn]; x1 += resid[rA * N + gn + 1];
                y0 += resid[rB * N + gn]; y1 += resid[rB * N + gn + 1];
                *(float2*)(C + rA * ldc + gn) = make_float2(x0, x1);
                *(float2*)(C + rB * ldc + gn) = make_float2(y0, y1);
            }
        }
    }

    if ((FLAGS & 64) && iscs) {
        float* scol = (float*)smem;
        const int contrib = (wid & 1) * 8 + (lane >> 2);
        __syncthreads();
#pragma unroll
        for (int nf = 0; nf < 4; nf++) {
            int cw = warpN + nf * 8 + (lane & 3) * 2;
            scol[(cw + 0) * 16 + contrib] = colsum[nf * 2];
            scol[(cw + 1) * 16 + contrib] = colsum[nf * 2 + 1];
        }
        __syncthreads();
        if (tid < 128) {
            float s = 0.f;
#pragma unroll
            for (int j = 0; j < 16; j++) s += scol[tid * 16 + j];
            g_tpart[(size_t)blockIdx.y * CH + n0 + tid] = s;
        }
    }
}

// ---------------- conversions ----------------
__global__ void __launch_bounds__(256) icvt_k(const float* __restrict__ src,
                                              uint16_t* __restrict__ p) {
    size_t i = (size_t)blockIdx.x * 256 + threadIdx.x;
    float4 v = ((const float4*)src)[i];
    ((uint2*)p)[i] = pack4h(v);
}

// one 32x32 transpose+cvt tile
__device__ __forceinline__ void wtile(const float* W, uint16_t* Hp,
                                      int K, int N, int n0, int k0) {
    __shared__ float tile[32][33];
    int tx = threadIdx.x & 31, ty = threadIdx.x >> 5;
#pragma unroll
    for (int i = 0; i < 4; i++)
        tile[ty + 8 * i][tx] = W[(size_t)(k0 + ty + 8 * i) * N + n0 + tx];
    __syncthreads();
#pragma unroll
    for (int i = 0; i < 4; i++) {
        __half h = __float2half_rn(tile[tx][ty + 8 * i]);
        Hp[(size_t)(n0 + ty + 8 * i) * K + k0 + tx] = *(uint16_t*)&h;
    }
}

// all six weight conversions in one launch
// region block counts: csum 4096 | wx 1024 | wg 1152 | wf1 1536 | wf2 512 | wo 1024  (total 9344)
__global__ void __launch_bounds__(256) wconv_k(
    const float* __restrict__ Wcs, const float* __restrict__ Wx,
    const float* __restrict__ Wg,  const float* __restrict__ Wf1,
    const float* __restrict__ Wf2, const float* __restrict__ Wo)
{
    int id = blockIdx.x;
    if (id < 4096) {                       // W_csum [1024][4096] -> wcsx[0..CH)
        int nx = id & 127, ky = id >> 7;   // Nb=128
        wtile(Wcs, wcsx, ISZ, CH, nx * 32, ky * 32);
    } else if ((id -= 4096) < 1024) {      // W_x [1024][1024] -> wcsx+CH*ISZ
        int nx = id & 31, ky = id >> 5;    // Nb=32
        wtile(Wx, wcsx + (size_t)CH * ISZ, ISZ, ISZ, nx * 32, ky * 32);
    } else if ((id -= 1024) < 1152) {      // W_g [8][384][384] -> wgf1 (per-head stride (TGD+FGD)*TGD)
        int zz = id / 144, rem = id % 144;
        int nx = rem % 12, ky = rem / 12;
        wtile(Wg + (size_t)zz * TGD * TGD,
              wgf1 + (size_t)zz * (TGD + FGD) * TGD, TGD, TGD, nx * 32, ky * 32);
    } else if ((id -= 1152) < 1536) {      // W_f1 [8][384][512] -> wgf1 + TGD*TGD
        int zz = id / 192, rem = id % 192;
        int nx = rem % 16, ky = rem / 16;
        wtile(Wf1 + (size_t)zz * TGD * FGD,
              wgf1 + (size_t)zz * (TGD + FGD) * TGD + (size_t)TGD * TGD, TGD, FGD, nx * 32, ky * 32);
    } else if ((id -= 1536) < 512) {       // W_f2 [8][512][128] -> wf2_p
        int zz = id / 64, rem = id % 64;
        int nx = rem % 4, ky = rem / 4;
        wtile(Wf2 + (size_t)zz * FGD * IGD,
              wf2_p + (size_t)zz * IGD * FGD, FGD, IGD, nx * 32, ky * 32);
    } else {                               // W_o [1024][1024] -> wo_p
        id -= 512;
        int nx = id & 31, ky = id >> 5;
        wtile(Wo, wo_p, ISZ, ISZ, nx * 32, ky * 32);
    }
}

// ---------------- block reduce ----------------
__device__ __forceinline__ void block_reduce2(float& a, float& b) {
    __shared__ float sh[64];
    int lane = threadIdx.x & 31, wid = threadIdx.x >> 5;
#pragma unroll
    for (int o = 16; o > 0; o >>= 1) {
        a += __shfl_xor_sync(0xffffffffu, a, o);
        b += __shfl_xor_sync(0xffffffffu, b, o);
    }
    if (lane == 0) { sh[wid] = a; sh[32 + wid] = b; }
    __syncthreads();
    if (threadIdx.x < 32) {
        a = (lane < 8) ? sh[lane] : 0.f;
        b = (lane < 8) ? sh[32 + lane] : 0.f;
#pragma unroll
        for (int o = 4; o > 0; o >>= 1) {
            a += __shfl_xor_sync(0xffffffffu, a, o);
            b += __shfl_xor_sync(0xffffffffu, b, o);
        }
        if (lane == 0) { sh[0] = a; sh[32] = b; }
    }
    __syncthreads();
    a = sh[0]; b = sh[32];
}

// ---------------- segmented cumsum (fp32, in place; tile sums inlined) ----------------
__global__ void __launch_bounds__(256) cumsumC_k() {
    int idx = blockIdx.x * 256 + threadIdx.x;
    int c = idx & 4095;
    int t = idx >> 12;
    int b = t >> 3, seg = t & 7;
    float* p = g_csum + ((size_t)b << 24) + (size_t)(seg * SEGL) * CH + c;
    float acc = 0.f;
    if (c < 2048) {
#pragma unroll
        for (int s2 = 0; s2 < NSEG; s2++)
            if (s2 < seg) {
                int t0 = (b * NSEG + s2) * 4;
                acc += g_tpart[(size_t)t0 * CH + c] + g_tpart[(size_t)(t0 + 1) * CH + c]
                     + g_tpart[(size_t)(t0 + 2) * CH + c] + g_tpart[(size_t)(t0 + 3) * CH + c];
            }
#pragma unroll 8
        for (int i = 0; i < SEGL; i++) { acc += p[(size_t)i * CH]; p[(size_t)i * CH] = acc; }
    } else {
#pragma unroll
        for (int s2 = 0; s2 < NSEG; s2++)
            if (s2 > seg) {
                int t0 = (b * NSEG + s2) * 4;
                acc += g_tpart[(size_t)t0 * CH + c] + g_tpart[(size_t)(t0 + 1) * CH + c]
                     + g_tpart[(size_t)(t0 + 2) * CH + c] + g_tpart[(size_t)(t0 + 3) * CH + c];
            }
#pragma unroll 8
        for (int i = SEGL - 1; i >= 0; i--) { acc += p[(size_t)i * CH]; p[(size_t)i * CH] = acc; }
    }
}

// ---------------- LN lc/rc -> cell plane + relu'd lci/rci (fp16) ----------------
__global__ void __launch_bounds__(256) ln_lcrc_k(
    const float* __restrict__ gl, const float* __restrict__ bl,
    const float* __restrict__ gr, const float* __restrict__ br_)
{
    const int row = blockIdx.x, side = blockIdx.y;
    const float4* x4 = (const float4*)(g_csum + (size_t)row * CH + side * 2048);
    float4 v[2];
    float s = 0.f, ss = 0.f;
#pragma unroll
    for (int k = 0; k < 2; k++) {
        v[k] = x4[threadIdx.x + k * 256];
        s  += v[k].x + v[k].y + v[k].z + v[k].w;
        ss += v[k].x * v[k].x + v[k].y * v[k].y + v[k].z * v[k].z + v[k].w * v[k].w;
    }
    block_reduce2(s, ss);
    float m  = s * (1.f / 2048.f);
    float rs = rsqrtf(ss * (1.f / 2048.f) - m * m + 1e-6f);

    const float4* g4 = (const float4*)(side ? gr  : gl);
    const float4* b4 = (const float4*)(side ? br_ : bl);
    uint16_t* ibuf = side ? rci16 : lci16;
#pragma unroll
    for (int k = 0; k < 2; k++) {
        int c4 = threadIdx.x + k * 256;
        int c  = c4 * 4;
        float4 gv = g4[c4], bv = b4[c4], xv = v[k];
        float4 o;
        o.x = (xv.x - m) * rs * gv.x + bv.x;
        o.y = (xv.y - m) * rs * gv.y + bv.y;
        o.z = (xv.z - m) * rs * gv.z + bv.z;
        o.w = (xv.w - m) * rs * gv.w + bv.w;
        if (c < 1024) {
            int h = c >> 7, ig = c & 127;
            size_t o16 = (size_t)row * (NHD * TGD) + h * TGD + side * 256 + ig;
            *(uint2*)&cell_p[o16] = pack4h(o);
        } else {
            o.x = fmaxf(o.x, 0.f); o.y = fmaxf(o.y, 0.f);
            o.z = fmaxf(o.z, 0.f); o.w = fmaxf(o.w, 0.f);
            *(uint2*)&ibuf[(size_t)row * ISZ + (c - 1024)] = pack4h(o);
        }
    }
}

// ---------------- merged LN: y==0 gates+sigmoid (in place); y==1 ffn+relu ----------------
__global__ void __launch_bounds__(256) ln_gf_k(
    const float* __restrict__ gg, const float* __restrict__ bg,
    const float* __restrict__ gf, const float* __restrict__ bf)
{
    const int row = blockIdx.x;
    if (blockIdx.y == 0) {
        uint2* x2 = (uint2*)(gate16 + (size_t)row * (NHD * TGD));
        float4 v[3];
        float s = 0.f, ss = 0.f;
#pragma unroll
        for (int k = 0; k < 3; k++) {
            uint2 u = x2[threadIdx.x + k * 256];
            float2 a = unp2(u.x), b = unp2(u.y);
            v[k] = make_float4(a.x, a.y, b.x, b.y);
            s  += v[k].x + v[k].y + v[k].z + v[k].w;
            ss += v[k].x * v[k].x + v[k].y * v[k].y + v[k].z * v[k].z + v[k].w * v[k].w;
        }
        block_reduce2(s, ss);
        float m  = s * (1.f / 3072.f);
        float rs = rsqrtf(ss * (1.f / 3072.f) - m * m + 1e-6f);
        const float4* g4 = (const float4*)gg;
        const float4* b4 = (const float4*)bg;
#pragma unroll
        for (int k = 0; k < 3; k++) {
            int c4 = threadIdx.x + k * 256;
            float4 gv = g4[c4], bv = b4[c4], xv = v[k];
            float4 o;
            o.x = 1.f / (1.f + __expf(-((xv.x - m) * rs * gv.x + bv.x)));
            o.y = 1.f / (1.f + __expf(-((xv.y - m) * rs * gv.y + bv.y)));
            o.z = 1.f / (1.f + __expf(-((xv.z - m) * rs * gv.z + bv.z)));
            o.w = 1.f / (1.f + __expf(-((xv.w - m) * rs * gv.w + bv.w)));
            uint2 w;
            w.x = pack2h(o.x, o.y);
            w.y = pack2h(o.z, o.w);
            x2[c4] = w;
        }
    } else {
        const uint2* x2 = (const uint2*)(hpre_p + (size_t)row * (NHD * FGD));
        float4 v[4];
        float s = 0.f, ss = 0.f;
#pragma unroll
        for (int k = 0; k < 4; k++) {
            uint2 u = x2[threadIdx.x + k * 256];
            float2 a = unp2(u.x), b = unp2(u.y);
            v[k] = make_float4(a.x, a.y, b.x, b.y);
            s  += v[k].x + v[k].y + v[k].z + v[k].w;
            ss += v[k].x * v[k].x + v[k].y * v[k].y + v[k].z * v[k].z + v[k].w * v[k].w;
        }
        block_reduce2(s, ss);
        float m  = s * (1.f / 4096.f);
        float rs = rsqrtf(ss * (1.f / 4096.f) - m * m + 1e-6f);
        const float4* g4 = (const float4*)gf;
        const float4* b4 = (const float4*)bf;
#pragma unroll
        for (int k = 0; k < 4; k++) {
            int c4 = threadIdx.x + k * 256;
            float4 gv = g4[c4], bv = b4[c4], xv = v[k];
            float4 o;
            o.x = fmaxf((xv.x - m) * rs * gv.x + bv.x, 0.f);
            o.y = fmaxf((xv.y - m) * rs * gv.y + bv.y, 0.f);
            o.z = fmaxf((xv.z - m) * rs * gv.z + bv.z, 0.f);
            o.w = fmaxf((xv.w - m) * rs * gv.w + bv.w, 0.f);
            *(uint2*)&hp_p[(size_t)row * (NHD * FGD) + c4 * 4] = pack4h(o);
        }
    }
}

// ---------------- host ----------------
extern "C" void kernel_launch(void* const* d_in, const int* in_sizes, int n_in,
                              void* d_out, int out_size) {
    const float* inputs = (const float*)d_in[0];
    const unsigned char* mask = (const unsigned char*)d_in[1];
    const float* W_csum = (const float*)d_in[2];
    const float* b_csum = (const float*)d_in[3];
    const float* W_x    = (const float*)d_in[4];
    const float* b_x    = (const float*)d_in[5];
    const float* gl     = (const float*)d_in[6];
    const float* bel    = (const float*)d_in[7];
    const float* gr     = (const float*)d_in[8];
    const float* ber    = (const float*)d_in[9];
    const float* ggain  = (const float*)d_in[10];
    const float* beg    = (const float*)d_in[11];
    const float* gf     = (const float*)d_in[12];
    const float* bef    = (const float*)d_in[13];
    const float* W_g    = (const float*)d_in[14];
    const float* b_g    = (const float*)d_in[15];
    const float* W_f1   = (const float*)d_in[16];
    const float* b_f1   = (const float*)d_in[17];
    const float* W_f2   = (const float*)d_in[18];
    const float* b_f2   = (const float*)d_in[19];
    const float* W_o    = (const float*)d_in[20];
    const float* b_o    = (const float*)d_in[21];
    float* out = (float*)d_out;

    uint16_t *pg16, *pl16, *pr16;
    cudaGetSymbolAddress((void**)&pg16,  gate16);
    cudaGetSymbolAddress((void**)&pl16,  lci16);
    cudaGetSymbolAddress((void**)&pr16,  rci16);
    uint16_t *pis, *pcell, *php, *ppre;
    uint16_t *pwcsx, *pwgf1, *pwf2, *pwo;
    cudaGetSymbolAddress((void**)&pis,   is_p);
    cudaGetSymbolAddress((void**)&pcell, cell_p);
    cudaGetSymbolAddress((void**)&php,   hp_p);
    cudaGetSymbolAddress((void**)&ppre,  pre_p);
    cudaGetSymbolAddress((void**)&pwcsx, wcsx);
    cudaGetSymbolAddress((void**)&pwgf1, wgf1);
    cudaGetSymbolAddress((void**)&pwf2,  wf2_p);
    cudaGetSymbolAddress((void**)&pwo,   wo_p);

    cudaFuncSetAttribute(hgemm_k<64>,  cudaFuncAttributeMaxDynamicSharedMemorySize, SMT);
    cudaFuncSetAttribute(hgemm_k<128>, cudaFuncAttributeMaxDynamicSharedMemorySize, SMT);
    cudaFuncSetAttribute(hgemm_k<8>,   cudaFuncAttributeMaxDynamicSharedMemorySize, SMT);
    cudaFuncSetAttribute(hgemm_k<2>,   cudaFuncAttributeMaxDynamicSharedMemorySize, SMT);

    dim3 blk(256);

    // 0) input convert  1) all weight conversions (one launch)
    icvt_k<<<ROWS * ISZ / 1024, blk>>>(inputs, pis);
    wconv_k<<<9344, blk>>>(W_csum, W_x, W_g, W_f1, W_f2, W_o);

    // 2) combined csum + out_x GEMM (N = 5120)
    hgemm_k<64><<<dim3((CH + ISZ) / 128, ROWS / 128, 1), blk, SMT>>>(
        pis, ISZ, 0, pwcsx, 0, b_csum, 0,
        nullptr, CH, 0, nullptr, CH + ISZ, ISZ, mask, b_x, nullptr, nullptr, nullptr);
    // 3) segmented scan (tile sums inlined)
    cumsumC_k<<<512, 256>>>();
    // 4) LN lc/rc -> cell + fp16 lci/rci
    ln_lcrc_k<<<dim3(ROWS, 2), 256>>>(gl, bel, gr, ber);
    // 5) combined gates + ffn1 GEMM (captured by ncu -s 5)
    hgemm_k<128><<<dim3((TGD + FGD) / 128, ROWS / 128, NHD), blk, SMT>>>(
        pcell, NHD * TGD, TGD, pwgf1, (long)(TGD + FGD) * TGD, b_g, TGD,
        nullptr, 0, 0, nullptr, TGD + FGD, TGD, nullptr, b_f1, nullptr, nullptr, nullptr);
    // 6) merged LN gates+sigmoid / LN ffn+relu
    ln_gf_k<<<dim3(ROWS, 2), 256>>>(ggain, beg, gf, bef);
    // 7) ffn2 GEMM + fused combine -> pre plane
    hgemm_k<8><<<dim3(IGD / 128, ROWS / 128, NHD), blk, SMT>>>(
        php, NHD * FGD, FGD, pwf2, (long)IGD * FGD, b_f2, IGD,
        nullptr, ISZ, IGD, nullptr, IGD, FGD, nullptr, nullptr, pg16, pl16, pr16);
    // 8) final GEMM + residual
    hgemm_k<2><<<dim3(ISZ / 128, ROWS / 128, 1), blk, SMT>>>(
        ppre, ISZ, 0, pwo, 0, b_o, 0,
        out, ISZ, 0, nullptr, ISZ, ISZ, nullptr, inputs, nullptr, nullptr, nullptr);
}

// round 17
// speedup vs baseline: 1.6896x; 1.0047x over previous
#include <cuda_runtime.h>
#include <cuda_fp16.h>
#include <cstdint>

#define ROWS 16384      // B*S
#define CH   4096
#define NHD  8
#define IGD  128
#define TGD  384
#define FGD  512
#define ISZ  1024
#define NSEG 16
#define SEGL 256        // 4096 / NSEG
#define NTILE (ROWS / 128)

// ---------------- scratch ----------------
__device__ float g_csum[(size_t)ROWS * CH];
__device__ float g_tpart[(size_t)NTILE * CH];

__device__ __align__(16) uint16_t gate16[(size_t)ROWS * NHD * TGD];
__device__ __align__(16) uint16_t lci16 [(size_t)ROWS * ISZ];
__device__ __align__(16) uint16_t rci16 [(size_t)ROWS * ISZ];

// ---------------- activation planes: single fp16 ----------------
__device__ __align__(16) uint16_t is_p  [(size_t)ROWS * ISZ];
__device__ __align__(16) uint16_t cell_p[(size_t)ROWS * NHD * TGD];
__device__ __align__(16) uint16_t hpre_p[(size_t)ROWS * NHD * FGD];
__device__ __align__(16) uint16_t hp_p  [(size_t)ROWS * NHD * FGD];
__device__ __align__(16) uint16_t pre_p [(size_t)ROWS * ISZ];
// ---------------- weight planes: fp16, transposed [N][K]; combined ----------------
__device__ __align__(16) uint16_t wcsx [(size_t)(CH + ISZ) * ISZ];
__device__ __align__(16) uint16_t wgf1 [(size_t)NHD * (TGD + FGD) * TGD];
__device__ __align__(16) uint16_t wf2_p[(size_t)NHD * IGD * FGD];
__device__ __align__(16) uint16_t wo_p [(size_t)ISZ * ISZ];

// ---------------- helpers ----------------
__device__ __forceinline__ uint32_t smem_u32(const void* p) {
    uint32_t a;
    asm("{ .reg .u64 t; cvta.to.shared.u64 t, %1; cvt.u32.u64 %0, t; }" : "=r"(a) : "l"(p));
    return a;
}
#define CP16(dst, src) asm volatile("cp.async.cg.shared.global [%0], [%1], 16;" :: "r"(dst), "l"(src))
#define CP_COMMIT()    asm volatile("cp.async.commit_group;" ::: "memory")

__device__ __forceinline__ void ldm4(uint32_t& r0, uint32_t& r1, uint32_t& r2, uint32_t& r3, uint32_t a) {
    asm volatile("ldmatrix.sync.aligned.m8n8.x4.shared.b16 {%0,%1,%2,%3}, [%4];"
                 : "=r"(r0), "=r"(r1), "=r"(r2), "=r"(r3) : "r"(a));
}
__device__ __forceinline__ void mma16816(float* d, const uint32_t* a, const uint32_t* b) {
    asm volatile("mma.sync.aligned.m16n8k16.row.col.f32.f16.f16.f32 "
                 "{%0,%1,%2,%3},{%4,%5,%6,%7},{%8,%9},{%0,%1,%2,%3};"
                 : "+f"(d[0]), "+f"(d[1]), "+f"(d[2]), "+f"(d[3])
                 : "r"(a[0]), "r"(a[1]), "r"(a[2]), "r"(a[3]), "r"(b[0]), "r"(b[1]));
}
__device__ __forceinline__ uint32_t pack2h(float x, float y) {
    __half2 v = __floats2half2_rn(x, y);
    return *(uint32_t*)&v;
}
__device__ __forceinline__ uint2 pack4h(float4 v) {
    uint2 r;
    r.x = pack2h(v.x, v.y);
    r.y = pack2h(v.z, v.w);
    return r;
}
__device__ __forceinline__ float2 unp2(uint32_t u) { return __half22float2(*(__half2*)&u); }

// ---------------- fp16 tensor-core GEMM, double-buffered ----------------
// FLAGS: 2 residual fp32-out (final); 8 fused-combine (ffn2);
//        64 combined csum+out_x; 128 combined gates+ffn1
#define P_A  0
#define P_B  8192
#define STG  16384
#define SMT  32768

template <int FLAGS>
__global__ void __launch_bounds__(256, 2) hgemm_k(
    const uint16_t* __restrict__ Ap, int lda, int aoff,
    const uint16_t* __restrict__ Bp, long boff,
    const float* __restrict__ bias, int biasoff,
    float* __restrict__ C, int ldc, int coff,
    uint16_t* __restrict__ Cp,
    int N, int K,
    const unsigned char* __restrict__ mask,
    const float* __restrict__ resid,          // FLAG2: residual; FLAG64: b_x; FLAG128: b_f1
    const uint16_t* __restrict__ g16,
    const uint16_t* __restrict__ l16, const uint16_t* __restrict__ r16)
{
    extern __shared__ char smem[];
    const uint32_t sb = smem_u32(smem);
    const int tid = threadIdx.x, wid = tid >> 5, lane = tid & 31;
    const int z = blockIdx.z;

    Ap += (long)z * aoff;
    Bp += (long)z * boff;
    bias += (long)z * biasoff;
    C  += (long)z * coff;

    const int m0 = blockIdx.y * 128;
    const int n0 = blockIdx.x * 128;
    const int warpM = (wid & 1) * 64;
    const int warpN = (wid >> 1) * 32;

    const int rowA = warpM + (lane & 15);
    const int hiA  = (lane >> 4) & 1;
    const int swA  = (rowA >> 1) & 3;
    const uint32_t aRow = sb + P_A + (uint32_t)rowA * 64;

    const int rowB = warpN + (lane & 7) + ((lane & 16) >> 1);
    const int hiB  = (lane >> 3) & 1;
    const int swB  = (rowB >> 1) & 3;
    const uint32_t bRow = sb + P_B + (uint32_t)rowB * 64;

    const int su0 = tid, su1 = tid + 256;
    const int sr0 = su0 >> 2, sc0 = su0 & 3;
    const int sr1 = su1 >> 2, sc1 = su1 & 3;
    const uint32_t sd0 = (uint32_t)sr0 * 64 + ((uint32_t)(sc0 ^ ((sr0 >> 1) & 3)) << 4);
    const uint32_t sd1 = (uint32_t)sr1 * 64 + ((uint32_t)(sc1 ^ ((sr1 >> 1) & 3)) << 4);

    float acc[4][4][4];
#pragma unroll
    for (int i = 0; i < 4; i++)
#pragma unroll
        for (int j = 0; j < 4; j++)
#pragma unroll
            for (int q = 0; q < 4; q++) acc[i][j][q] = 0.f;

    const int nch = K >> 5;

#define STAGE(c, bs) do { \
        const int _k0 = (c) << 5; \
        const uint32_t _b = sb + (bs) * STG; \
        size_t _sa = (size_t)(m0 + sr0) * lda + _k0 + sc0 * 8; \
        CP16(_b + P_A + sd0, Ap + _sa); \
        size_t _sb2 = (size_t)(n0 + sr0) * K + _k0 + sc0 * 8; \
        CP16(_b + P_B + sd0, Bp + _sb2); \
        _sa = (size_t)(m0 + sr1) * lda + _k0 + sc1 * 8; \
        CP16(_b + P_A + sd1, Ap + _sa); \
        _sb2 = (size_t)(n0 + sr1) * K + _k0 + sc1 * 8; \
        CP16(_b + P_B + sd1, Bp + _sb2); \
        CP_COMMIT(); \
    } while (0)

    STAGE(0, 0);
    for (int c = 0; c < nch; c++) {
        const int bs = c & 1;
        if (c + 1 < nch) {
            STAGE(c + 1, bs ^ 1);
            asm volatile("cp.async.wait_group 1;" ::: "memory");
        } else {
            asm volatile("cp.async.wait_group 0;" ::: "memory");
        }
        __syncthreads();

        const uint32_t bb = (uint32_t)bs * STG;
#pragma unroll
        for (int ks = 0; ks < 2; ks++) {
            const uint32_t ca = ((uint32_t)((2 * ks + hiA) ^ swA)) << 4;
            const uint32_t cb = ((uint32_t)((2 * ks + hiB) ^ swB)) << 4;
            uint32_t bf[4][2];
            ldm4(bf[0][0], bf[0][1], bf[1][0], bf[1][1], bRow + bb + cb);
            ldm4(bf[2][0], bf[2][1], bf[3][0], bf[3][1], bRow + bb + 1024 + cb);
#pragma unroll
            for (int mf = 0; mf < 4; mf++) {
                uint32_t af[4];
                ldm4(af[0], af[1], af[2], af[3], aRow + bb + mf * 1024 + ca);
#pragma unroll
                for (int nf = 0; nf < 4; nf++)
                    mma16816(acc[mf][nf], af, bf[nf]);
            }
        }
        __syncthreads();
    }
#undef STAGE

    // ---------------- epilogue ----------------
    const bool iscs = (FLAGS & 64) ? (n0 < CH) : false;
    const bool isg  = (FLAGS & 128) ? (n0 < TGD) : false;
    float colsum[8];
    if (FLAGS & 64) {
#pragma unroll
        for (int q = 0; q < 8; q++) colsum[q] = 0.f;
    }
#pragma unroll
    for (int mf = 0; mf < 4; mf++) {
        long rA = m0 + warpM + mf * 16 + (lane >> 2);
        long rB = rA + 8;
        float zfA = 1.f, zfB = 1.f;
        if (FLAGS & 64) {
            if (iscs) { zfA = mask[rA] ? 0.f : 1.f; zfB = mask[rB] ? 0.f : 1.f; }
        }
#pragma unroll
        for (int nf = 0; nf < 4; nf++) {
            int gn = n0 + warpN + nf * 8 + (lane & 3) * 2;
            float b0, b1;
            if (FLAGS & 64) {
                b0 = iscs ? bias[gn] : resid[gn - CH];
                b1 = iscs ? bias[gn + 1] : resid[gn - CH + 1];
            } else if (FLAGS & 128) {
                b0 = isg ? bias[gn] : resid[z * FGD + gn - TGD];
                b1 = isg ? bias[gn + 1] : resid[z * FGD + gn - TGD + 1];
            } else {
                b0 = bias[gn]; b1 = bias[gn + 1];
            }
            float x0 = acc[mf][nf][0] + b0, x1 = acc[mf][nf][1] + b1;
            float y0 = acc[mf][nf][2] + b0, y1 = acc[mf][nf][3] + b1;

            if (FLAGS & 64) {
                if (iscs) {
                    x0 *= zfA; x1 *= zfA; y0 *= zfB; y1 *= zfB;
                    colsum[nf * 2]     += x0 + y0;
                    colsum[nf * 2 + 1] += x1 + y1;
                    *(float2*)(g_csum + rA * CH + gn) = make_float2(x0, x1);
                    *(float2*)(g_csum + rB * CH + gn) = make_float2(y0, y1);
                } else {
                    int gx = gn - CH;
                    int cn = (gx >> 7) * TGD + IGD + (gx & 127);
                    *(uint32_t*)&cell_p[rA * (NHD * TGD) + cn] = pack2h(x0, x1);
                    *(uint32_t*)&cell_p[rB * (NHD * TGD) + cn] = pack2h(y0, y1);
                }
            } else if (FLAGS & 128) {
                if (isg) {
                    *(uint32_t*)&gate16[rA * (NHD * TGD) + z * TGD + gn] = pack2h(x0, x1);
                    *(uint32_t*)&gate16[rB * (NHD * TGD) + z * TGD + gn] = pack2h(y0, y1);
                } else {
                    int gx = gn - TGD;
                    *(uint32_t*)&hpre_p[rA * (NHD * FGD) + z * FGD + gx] = pack2h(x0, x1);
                    *(uint32_t*)&hpre_p[rB * (NHD * FGD) + z * FGD + gx] = pack2h(y0, y1);
                }
            } else if (FLAGS & 8) {
                int gc = z * IGD + gn;
                const uint16_t* gbA = g16 + rA * (NHD * TGD) + z * TGD;
                const uint16_t* gbB = g16 + rB * (NHD * TGD) + z * TGD;
                float2 lgA = unp2(*(const uint32_t*)&gbA[gn]);
                float2 igA = unp2(*(const uint32_t*)&gbA[IGD + gn]);
                float2 rgA = unp2(*(const uint32_t*)&gbA[2 * IGD + gn]);
                float2 lgB = unp2(*(const uint32_t*)&gbB[gn]);
                float2 igB = unp2(*(const uint32_t*)&gbB[IGD + gn]);
                float2 rgB = unp2(*(const uint32_t*)&gbB[2 * IGD + gn]);
                float2 liA = unp2(*(const uint32_t*)&l16[rA * ISZ + gc]);
                float2 riA = unp2(*(const uint32_t*)&r16[rA * ISZ + gc]);
                float2 liB = unp2(*(const uint32_t*)&l16[rB * ISZ + gc]);
                float2 riB = unp2(*(const uint32_t*)&r16[rB * ISZ + gc]);
                float o0 = liA.x * lgA.x + igA.x * x0 + riA.x * rgA.x;
                float o1 = liA.y * lgA.y + igA.y * x1 + riA.y * rgA.y;
                float o2 = liB.x * lgB.x + igB.x * y0 + riB.x * rgB.x;
                float o3 = liB.y * lgB.y + igB.y * y1 + riB.y * rgB.y;
                *(uint32_t*)&pre_p[rA * ISZ + gc] = pack2h(o0, o1);
                *(uint32_t*)&pre_p[rB * ISZ + gc] = pack2h(o2, o3);
            } else {
                x0 += resid[rA * N + gn]; x1 += resid[rA * N + gn + 1];
                y0 += resid[rB * N + gn]; y1 += resid[rB * N + gn + 1];
                *(float2*)(C + rA * ldc + gn) = make_float2(x0, x1);
                *(float2*)(C + rB * ldc + gn) = make_float2(y0, y1);
            }
        }
    }

    if ((FLAGS & 64) && iscs) {
        float* scol = (float*)smem;
        const int contrib = (wid & 1) * 8 + (lane >> 2);
        __syncthreads();
#pragma unroll
        for (int nf = 0; nf < 4; nf++) {
            int cw = warpN + nf * 8 + (lane & 3) * 2;
            scol[(cw + 0) * 16 + contrib] = colsum[nf * 2];
            scol[(cw + 1) * 16 + contrib] = colsum[nf * 2 + 1];
        }
        __syncthreads();
        if (tid < 128) {
            float s = 0.f;
#pragma unroll
            for (int j = 0; j < 16; j++) s += scol[tid * 16 + j];
            g_tpart[(size_t)blockIdx.y * CH + n0 + tid] = s;
        }
    }
}

// ---------------- conversions ----------------
__global__ void __launch_bounds__(256) icvt_k(const float* __restrict__ src,
                                              uint16_t* __restrict__ p) {
    size_t i = (size_t)blockIdx.x * 256 + threadIdx.x;
    float4 v = ((const float4*)src)[i];
    ((uint2*)p)[i] = pack4h(v);
}

__device__ __forceinline__ void wtile(const float* W, uint16_t* Hp,
                                      int K, int N, int n0, int k0) {
    __shared__ float tile[32][33];
    int tx = threadIdx.x & 31, ty = threadIdx.x >> 5;
#pragma unroll
    for (int i = 0; i < 4; i++)
        tile[ty + 8 * i][tx] = W[(size_t)(k0 + ty + 8 * i) * N + n0 + tx];
    __syncthreads();
#pragma unroll
    for (int i = 0; i < 4; i++) {
        __half h = __float2half_rn(tile[tx][ty + 8 * i]);
        Hp[(size_t)(n0 + ty + 8 * i) * K + k0 + tx] = *(uint16_t*)&h;
    }
}

// all six weight conversions in one launch (9344 blocks)
__global__ void __launch_bounds__(256) wconv_k(
    const float* __restrict__ Wcs, const float* __restrict__ Wx,
    const float* __restrict__ Wg,  const float* __restrict__ Wf1,
    const float* __restrict__ Wf2, const float* __restrict__ Wo)
{
    int id = blockIdx.x;
    if (id < 4096) {
        int nx = id & 127, ky = id >> 7;
        wtile(Wcs, wcsx, ISZ, CH, nx * 32, ky * 32);
    } else if ((id -= 4096) < 1024) {
        int nx = id & 31, ky = id >> 5;
        wtile(Wx, wcsx + (size_t)CH * ISZ, ISZ, ISZ, nx * 32, ky * 32);
    } else if ((id -= 1024) < 1152) {
        int zz = id / 144, rem = id % 144;
        int nx = rem % 12, ky = rem / 12;
        wtile(Wg + (size_t)zz * TGD * TGD,
              wgf1 + (size_t)zz * (TGD + FGD) * TGD, TGD, TGD, nx * 32, ky * 32);
    } else if ((id -= 1152) < 1536) {
        int zz = id / 192, rem = id % 192;
        int nx = rem % 16, ky = rem / 16;
        wtile(Wf1 + (size_t)zz * TGD * FGD,
              wgf1 + (size_t)zz * (TGD + FGD) * TGD + (size_t)TGD * TGD, TGD, FGD, nx * 32, ky * 32);
    } else if ((id -= 1536) < 512) {
        int zz = id / 64, rem = id % 64;
        int nx = rem % 4, ky = rem / 4;
        wtile(Wf2 + (size_t)zz * FGD * IGD,
              wf2_p + (size_t)zz * IGD * FGD, FGD, IGD, nx * 32, ky * 32);
    } else {
        id -= 512;
        int nx = id & 31, ky = id >> 5;
        wtile(Wo, wo_p, ISZ, ISZ, nx * 32, ky * 32);
    }
}

// ---------------- block reduce ----------------
__device__ __forceinline__ void block_reduce2(float& a, float& b) {
    __shared__ float sh[64];
    int lane = threadIdx.x & 31, wid = threadIdx.x >> 5;
#pragma unroll
    for (int o = 16; o > 0; o >>= 1) {
        a += __shfl_xor_sync(0xffffffffu, a, o);
        b += __shfl_xor_sync(0xffffffffu, b, o);
    }
    if (lane == 0) { sh[wid] = a; sh[32 + wid] = b; }
    __syncthreads();
    if (threadIdx.x < 32) {
        a = (lane < 8) ? sh[lane] : 0.f;
        b = (lane < 8) ? sh[32 + lane] : 0.f;
#pragma unroll
        for (int o = 4; o > 0; o >>= 1) {
            a += __shfl_xor_sync(0xffffffffu, a, o);
            b += __shfl_xor_sync(0xffffffffu, b, o);
        }
        if (lane == 0) { sh[0] = a; sh[32] = b; }
    }
    __syncthreads();
    a = sh[0]; b = sh[32];
}

// ---------------- segmented cumsum: NSEG=16, float2 lanes, fp32 in place ----------------
// 131072 threads: (b*NSEG+seg)*2048 + c2 ; cols 2*c2, 2*c2+1. Tiles/segment = 2.
__global__ void __launch_bounds__(256) cumsumC_k() {
    int idx = blockIdx.x * 256 + threadIdx.x;
    int c2 = idx & 2047;
    int t = idx >> 11;
    int b = t >> 4, seg = t & 15;
    float2* p = (float2*)(g_csum + ((size_t)b << 24) + (size_t)(seg * SEGL) * CH) + c2;
    const float2* tp = (const float2*)g_tpart;
    float ax = 0.f, ay = 0.f;
    const int tb = b * (NTILE / 4);           // first tile of this batch (32 tiles/batch)
    if (c2 < 1024) {    // forward half (cols < 2048)
#pragma unroll
        for (int s2 = 0; s2 < NSEG; s2++)
            if (s2 < seg) {
                int t0 = tb + s2 * 2;
                float2 f0 = tp[(size_t)t0 * (CH / 2) + c2];
                float2 f1 = tp[(size_t)(t0 + 1) * (CH / 2) + c2];
                ax += f0.x + f1.x; ay += f0.y + f1.y;
            }
#pragma unroll 8
        for (int i = 0; i < SEGL; i++) {
            float2 f = p[(size_t)i * (CH / 2)];
            ax += f.x; ay += f.y;
            p[(size_t)i * (CH / 2)] = make_float2(ax, ay);
        }
    } else {            // reverse half
#pragma unroll
        for (int s2 = 0; s2 < NSEG; s2++)
            if (s2 > seg) {
                int t0 = tb + s2 * 2;
                float2 f0 = tp[(size_t)t0 * (CH / 2) + c2];
                float2 f1 = tp[(size_t)(t0 + 1) * (CH / 2) + c2];
                ax += f0.x + f1.x; ay += f0.y + f1.y;
            }
#pragma unroll 8
        for (int i = SEGL - 1; i >= 0; i--) {
            float2 f = p[(size_t)i * (CH / 2)];
            ax += f.x; ay += f.y;
            p[(size_t)i * (CH / 2)] = make_float2(ax, ay);
        }
    }
}

// ---------------- LN lc/rc -> cell plane + relu'd lci/rci (fp16) ----------------
__global__ void __launch_bounds__(256) ln_lcrc_k(
    const float* __restrict__ gl, const float* __restrict__ bl,
    const float* __restrict__ gr, const float* __restrict__ br_)
{
    const int row = blockIdx.x, side = blockIdx.y;
    const float4* x4 = (const float4*)(g_csum + (size_t)row * CH + side * 2048);
    float4 v[2];
    float s = 0.f, ss = 0.f;
#pragma unroll
    for (int k = 0; k < 2; k++) {
        v[k] = x4[threadIdx.x + k * 256];
        s  += v[k].x + v[k].y + v[k].z + v[k].w;
        ss += v[k].x * v[k].x + v[k].y * v[k].y + v[k].z * v[k].z + v[k].w * v[k].w;
    }
    block_reduce2(s, ss);
    float m  = s * (1.f / 2048.f);
    float rs = rsqrtf(ss * (1.f / 2048.f) - m * m + 1e-6f);

    const float4* g4 = (const float4*)(side ? gr  : gl);
    const float4* b4 = (const float4*)(side ? br_ : bl);
    uint16_t* ibuf = side ? rci16 : lci16;
#pragma unroll
    for (int k = 0; k < 2; k++) {
        int c4 = threadIdx.x + k * 256;
        int c  = c4 * 4;
        float4 gv = g4[c4], bv = b4[c4], xv = v[k];
        float4 o;
        o.x = (xv.x - m) * rs * gv.x + bv.x;
        o.y = (xv.y - m) * rs * gv.y + bv.y;
        o.z = (xv.z - m) * rs * gv.z + bv.z;
        o.w = (xv.w - m) * rs * gv.w + bv.w;
        if (c < 1024) {
            int h = c >> 7, ig = c & 127;
            size_t o16 = (size_t)row * (NHD * TGD) + h * TGD + side * 256 + ig;
            *(uint2*)&cell_p[o16] = pack4h(o);
        } else {
            o.x = fmaxf(o.x, 0.f); o.y = fmaxf(o.y, 0.f);
            o.z = fmaxf(o.z, 0.f); o.w = fmaxf(o.w, 0.f);
            *(uint2*)&ibuf[(size_t)row * ISZ + (c - 1024)] = pack4h(o);
        }
    }
}

// ---------------- merged LN: y==0 gates+sigmoid (in place); y==1 ffn+relu ----------------
__global__ void __launch_bounds__(256) ln_gf_k(
    const float* __restrict__ gg, const float* __restrict__ bg,
    const float* __restrict__ gf, const float* __restrict__ bf)
{
    const int row = blockIdx.x;
    if (blockIdx.y == 0) {
        uint2* x2 = (uint2*)(gate16 + (size_t)row * (NHD * TGD));
        float4 v[3];
        float s = 0.f, ss = 0.f;
#pragma unroll
        for (int k = 0; k < 3; k++) {
            uint2 u = x2[threadIdx.x + k * 256];
            float2 a = unp2(u.x), b = unp2(u.y);
            v[k] = make_float4(a.x, a.y, b.x, b.y);
            s  += v[k].x + v[k].y + v[k].z + v[k].w;
            ss += v[k].x * v[k].x + v[k].y * v[k].y + v[k].z * v[k].z + v[k].w * v[k].w;
        }
        block_reduce2(s, ss);
        float m  = s * (1.f / 3072.f);
        float rs = rsqrtf(ss * (1.f / 3072.f) - m * m + 1e-6f);
        const float4* g4 = (const float4*)gg;
        const float4* b4 = (const float4*)bg;
#pragma unroll
        for (int k = 0; k < 3; k++) {
            int c4 = threadIdx.x + k * 256;
            float4 gv = g4[c4], bv = b4[c4], xv = v[k];
            float4 o;
            o.x = 1.f / (1.f + __expf(-((xv.x - m) * rs * gv.x + bv.x)));
            o.y = 1.f / (1.f + __expf(-((xv.y - m) * rs * gv.y + bv.y)));
            o.z = 1.f / (1.f + __expf(-((xv.z - m) * rs * gv.z + bv.z)));
            o.w = 1.f / (1.f + __expf(-((xv.w - m) * rs * gv.w + bv.w)));
            uint2 w;
            w.x = pack2h(o.x, o.y);
            w.y = pack2h(o.z, o.w);
            x2[c4] = w;
        }
    } else {
        const uint2* x2 = (const uint2*)(hpre_p + (size_t)row * (NHD * FGD));
        float4 v[4];
        float s = 0.f, ss = 0.f;
#pragma unroll
        for (int k = 0; k < 4; k++) {
            uint2 u = x2[threadIdx.x + k * 256];
            float2 a = unp2(u.x), b = unp2(u.y);
            v[k] = make_float4(a.x, a.y, b.x, b.y);
            s  += v[k].x + v[k].y + v[k].z + v[k].w;
            ss += v[k].x * v[k].x + v[k].y * v[k].y + v[k].z * v[k].z + v[k].w * v[k].w;
        }
        block_reduce2(s, ss);
        float m  = s * (1.f / 4096.f);
        float rs = rsqrtf(ss * (1.f / 4096.f) - m * m + 1e-6f);
        const float4* g4 = (const float4*)gf;
        const float4* b4 = (const float4*)bf;
#pragma unroll
        for (int k = 0; k < 4; k++) {
            int c4 = threadIdx.x + k * 256;
            float4 gv = g4[c4], bv = b4[c4], xv = v[k];
            float4 o;
            o.x = fmaxf((xv.x - m) * rs * gv.x + bv.x, 0.f);
            o.y = fmaxf((xv.y - m) * rs * gv.y + bv.y, 0.f);
            o.z = fmaxf((xv.z - m) * rs * gv.z + bv.z, 0.f);
            o.w = fmaxf((xv.w - m) * rs * gv.w + bv.w, 0.f);
            *(uint2*)&hp_p[(size_t)row * (NHD * FGD) + c4 * 4] = pack4h(o);
        }
    }
}

// ---------------- host ----------------
extern "C" void kernel_launch(void* const* d_in, const int* in_sizes, int n_in,
                              void* d_out, int out_size) {
    const float* inputs = (const float*)d_in[0];
    const unsigned char* mask = (const unsigned char*)d_in[1];
    const float* W_csum = (const float*)d_in[2];
    const float* b_csum = (const float*)d_in[3];
    const float* W_x    = (const float*)d_in[4];
    const float* b_x    = (const float*)d_in[5];
    const float* gl     = (const float*)d_in[6];
    const float* bel    = (const float*)d_in[7];
    const float* gr     = (const float*)d_in[8];
    const float* ber    = (const float*)d_in[9];
    const float* ggain  = (const float*)d_in[10];
    const float* beg    = (const float*)d_in[11];
    const float* gf     = (const float*)d_in[12];
    const float* bef    = (const float*)d_in[13];
    const float* W_g    = (const float*)d_in[14];
    const float* b_g    = (const float*)d_in[15];
    const float* W_f1   = (const float*)d_in[16];
    const float* b_f1   = (const float*)d_in[17];
    const float* W_f2   = (const float*)d_in[18];
    const float* b_f2   = (const float*)d_in[19];
    const float* W_o    = (const float*)d_in[20];
    const float* b_o    = (const float*)d_in[21];
    float* out = (float*)d_out;

    uint16_t *pg16, *pl16, *pr16;
    cudaGetSymbolAddress((void**)&pg16,  gate16);
    cudaGetSymbolAddress((void**)&pl16,  lci16);
    cudaGetSymbolAddress((void**)&pr16,  rci16);
    uint16_t *pis, *pcell, *php, *ppre;
    uint16_t *pwcsx, *pwgf1, *pwf2, *pwo;
    cudaGetSymbolAddress((void**)&pis,   is_p);
    cudaGetSymbolAddress((void**)&pcell, cell_p);
    cudaGetSymbolAddress((void**)&php,   hp_p);
    cudaGetSymbolAddress((void**)&ppre,  pre_p);
    cudaGetSymbolAddress((void**)&pwcsx, wcsx);
    cudaGetSymbolAddress((void**)&pwgf1, wgf1);
    cudaGetSymbolAddress((void**)&pwf2,  wf2_p);
    cudaGetSymbolAddress((void**)&pwo,   wo_p);

    cudaFuncSetAttribute(hgemm_k<64>,  cudaFuncAttributeMaxDynamicSharedMemorySize, SMT);
    cudaFuncSetAttribute(hgemm_k<128>, cudaFuncAttributeMaxDynamicSharedMemorySize, SMT);
    cudaFuncSetAttribute(hgemm_k<8>,   cudaFuncAttributeMaxDynamicSharedMemorySize, SMT);
    cudaFuncSetAttribute(hgemm_k<2>,   cudaFuncAttributeMaxDynamicSharedMemorySize, SMT);

    dim3 blk(256);

    // 0) input convert  1) all weight conversions (one launch)
    icvt_k<<<ROWS * ISZ / 1024, blk>>>(inputs, pis);
    wconv_k<<<9344, blk>>>(W_csum, W_x, W_g, W_f1, W_f2, W_o);

    // 2) combined csum + out_x GEMM (N = 5120)
    hgemm_k<64><<<dim3((CH + ISZ) / 128, ROWS / 128, 1), blk, SMT>>>(
        pis, ISZ, 0, pwcsx, 0, b_csum, 0,
        nullptr, CH, 0, nullptr, CH + ISZ, ISZ, mask, b_x, nullptr, nullptr, nullptr);
    // 3) segmented scan (NSEG=16, float2 lanes)
    cumsumC_k<<<512, 256>>>();
    // 4) LN lc/rc -> cell + fp16 lci/rci
    ln_lcrc_k<<<dim3(ROWS, 2), 256>>>(gl, bel, gr, ber);
    // 5) combined gates + ffn1 GEMM
    hgemm_k<128><<<dim3((TGD + FGD) / 128, ROWS / 128, NHD), blk, SMT>>>(
        pcell, NHD * TGD, TGD, pwgf1, (long)(TGD + FGD) * TGD, b_g, TGD,
        nullptr, 0, 0, nullptr, TGD + FGD, TGD, nullptr, b_f1, nullptr, nullptr, nullptr);
    // 6) merged LN gates+sigmoid / LN ffn+relu
    ln_gf_k<<<dim3(ROWS, 2), 256>>>(ggain, beg, gf, bef);
    // 7) ffn2 GEMM + fused combine -> pre plane
    hgemm_k<8><<<dim3(IGD / 128, ROWS / 128, NHD), blk, SMT>>>(
        php, NHD * FGD, FGD, pwf2, (long)IGD * FGD, b_f2, IGD,
        nullptr, ISZ, IGD, nullptr, IGD, FGD, nullptr, nullptr, pg16, pl16, pr16);
    // 8) final GEMM + residual
    hgemm_k<2><<<dim3(ISZ / 128, ROWS / 128, 1), blk, SMT>>>(
        ppre, ISZ, 0, pwo, 0, b_o, 0,
        out, ISZ, 0, nullptr, ISZ, ISZ, nullptr, inputs, nullptr, nullptr, nullptr);
}